// round 8
// baseline (speedup 1.0000x reference)
#include <cuda_runtime.h>
#include <cuda_fp16.h>
#include <math.h>
#include <stdint.h>

#define Bb   16
#define Nn   512
#define Dd   512
#define Hh   8
#define HDm  64
#define MR   (Bb*Nn)
#define DFF  2048

// ---------------- scratch (static device globals) ----------------
__device__ __half g_h1 [MR*Dd];
__device__ __half g_QKh[2*MR*Dd];     // [2][B][H][N][HD]
__device__ __half g_Vh [MR*Dd];       // [B][H][N][HD]
__device__ __half g_VTh[MR*Dd];       // [B][H][HD][N]
__device__ __half g_O  [MR*Dd];       // (B,N,D) half
__device__ float  g_x1 [MR*Dd];
__device__ __half g_h2 [MR*Dd];
__device__ __half g_mid[MR*DFF];
__device__ __half g_Wqkvh[3*Dd*Dd];   // [1536][512] K-major
__device__ __half g_WoTh [Dd*Dd];
__device__ __half g_W1Th [DFF*Dd];
__device__ __half g_W2Th [Dd*DFF];
__device__ float  g_bqkv[3*Dd];
__device__ uint8_t g_adjm[(size_t)Bb*Nn*Nn];  // adj*8 or 40 (masked)
__device__ int    g_adj_is32;

// ======================= helpers =======================
__device__ __forceinline__ uint32_t smem_u32(const void* p) {
    uint32_t a;
    asm("{ .reg .u64 t; cvta.to.shared.u64 t, %1; cvt.u32.u64 %0, t; }" : "=r"(a) : "l"(p));
    return a;
}
__device__ __forceinline__ void cp16h(void* s, const __half* g) {
    uint32_t sa = smem_u32(s);
    asm volatile("cp.async.cg.shared.global [%0], [%1], 16;" :: "r"(sa), "l"(g) : "memory");
}
#define CP_COMMIT() asm volatile("cp.async.commit_group;" ::: "memory")
#define CP_WAIT(n)  asm volatile("cp.async.wait_group %0;" :: "n"(n) : "memory")

__device__ __forceinline__ int swz3(int r) {          // bit-reverse of r&7
    return ((r & 1) << 2) | (r & 2) | ((r & 4) >> 2);
}
__device__ __forceinline__ uint32_t h2u(float a, float b) {
    __half2 v = __floats2half2_rn(a, b);
    return *reinterpret_cast<uint32_t*>(&v);
}

// m16n8k16 fp16 mma, f32 accum, row.col
__device__ __forceinline__ void mma16(float* c, uint32_t a0, uint32_t a1, uint32_t a2,
                                      uint32_t a3, uint32_t b0, uint32_t b1) {
    asm volatile("mma.sync.aligned.m16n8k16.row.col.f32.f16.f16.f32 "
        "{%0,%1,%2,%3},{%4,%5,%6,%7},{%8,%9},{%0,%1,%2,%3};"
        : "+f"(c[0]), "+f"(c[1]), "+f"(c[2]), "+f"(c[3])
        : "r"(a0), "r"(a1), "r"(a2), "r"(a3), "r"(b0), "r"(b1));
}

// 64x64 warp tile over one 64-k plane pair (A rows at pa, B rows at pb)
__device__ __forceinline__ void plane_mma4(const char* pa, const char* pb,
                                           float acc[4][8][4], int lq, int lr, int sl)
{
    #pragma unroll
    for (int sc = 0; sc < 2; sc++) {
        int go = ((sc * 4 + lr) ^ sl) << 4;
        uint4 Ar[4][2];
        #pragma unroll
        for (int mt = 0; mt < 4; mt++) {
            Ar[mt][0] = *reinterpret_cast<const uint4*>(pa + (mt*16 + lq    ) * 128 + go);
            Ar[mt][1] = *reinterpret_cast<const uint4*>(pa + (mt*16 + lq + 8) * 128 + go);
        }
        #pragma unroll
        for (int nt = 0; nt < 8; nt++) {
            uint4 Bv = *reinterpret_cast<const uint4*>(pb + (nt*8 + lq) * 128 + go);
            #pragma unroll
            for (int mt = 0; mt < 4; mt++) {
                mma16(acc[mt][nt], Ar[mt][0].x, Ar[mt][1].x, Ar[mt][0].y, Ar[mt][1].y, Bv.x, Bv.y);
                mma16(acc[mt][nt], Ar[mt][0].z, Ar[mt][1].z, Ar[mt][0].w, Ar[mt][1].w, Bv.z, Bv.w);
            }
        }
    }
}

// ======================= dense GEMM: CTA 128x128, 4 warps (64x64 each) ==========
#define DENSE_SMEM 65536

template<int MODE>
__global__ void __launch_bounds__(128, 2) hgemm(
    const __half* __restrict__ A, const __half* __restrict__ Wt,
    const float* __restrict__ bias, const float* __restrict__ res,
    const float* __restrict__ mask, void* Cv, int K, int ncols)
{
    extern __shared__ char sm[];
    const int tid = threadIdx.x, lane = tid & 31, warp = tid >> 5;
    const int wm = warp & 1, wn = warp >> 1, lq = lane >> 2, lr = lane & 3;
    const int bm = blockIdx.y * 128, bn = blockIdx.x * 128;
    const int sl = swz3(lq);

    float acc[4][8][4];
    #pragma unroll
    for (int i = 0; i < 4; i++)
        #pragma unroll
        for (int j = 0; j < 8; j++)
            #pragma unroll
            for (int l = 0; l < 4; l++) acc[i][j][l] = 0.0f;

    const int NC = K >> 6;

    auto loadc = [&](int c, int buf) {
        char* dA = sm + buf * 32768;
        char* dB = dA + 16384;
        int k0 = c << 6;
        #pragma unroll
        for (int i = 0; i < 8; i++) {
            int idx = tid + i * 128, row = idx >> 3, g = idx & 7;
            int gp = ((g ^ swz3(row & 7)) << 4);
            cp16h(dA + row * 128 + gp, A  + (size_t)(bm + row) * K + k0 + g * 8);
            cp16h(dB + row * 128 + gp, Wt + (size_t)(bn + row) * K + k0 + g * 8);
        }
    };
    loadc(0, 0); CP_COMMIT();
    loadc(1, 1); CP_COMMIT();

    for (int c = 0; c < NC; c++) {
        CP_WAIT(1);
        __syncthreads();
        const char* pa = sm + (c & 1) * 32768 + (wm * 64) * 128;
        const char* pb = sm + (c & 1) * 32768 + 16384 + (wn * 64) * 128;
        plane_mma4(pa, pb, acc, lq, lr, sl);
        __syncthreads();
        if (c + 2 < NC) loadc(c + 2, c & 1);
        CP_COMMIT();
    }

    #pragma unroll
    for (int mt = 0; mt < 4; mt++) {
        #pragma unroll
        for (int hf = 0; hf < 2; hf++) {
            int r = bm + wm*64 + mt*16 + lq + hf*8;
            float mr = (MODE == 3) ? mask[r] : 0.0f;
            #pragma unroll
            for (int nt = 0; nt < 8; nt++) {
                int cg = bn + wn*64 + nt*8 + 2*lr;
                float v0 = acc[mt][nt][hf*2 + 0] + bias[cg];
                float v1 = acc[mt][nt][hf*2 + 1] + bias[cg + 1];
                if (MODE == 0) {
                    int mat = cg >> 9, cc = cg & 511, hh = cc >> 6, d0 = cc & 63;
                    int b = r >> 9, n = r & 511;
                    if (mat == 0) { v0 *= 0.125f; v1 *= 0.125f; }  // pre-scale Q
                    __half2 hv = __floats2half2_rn(v0, v1);
                    if (mat < 2) {
                        __half* op = (__half*)Cv + ((((size_t)mat*Bb + b)*Hh + hh)*Nn + n)*HDm + d0;
                        *reinterpret_cast<__half2*>(op) = hv;
                    } else {
                        __half* vp = g_Vh + (((size_t)b*Hh + hh)*Nn + n)*HDm + d0;
                        *reinterpret_cast<__half2*>(vp) = hv;
                    }
                } else if (MODE == 1) {
                    float* C = (float*)Cv;
                    const float* rp = res + (size_t)r * ncols + cg;
                    float2 r2 = *reinterpret_cast<const float2*>(rp);
                    float2 o; o.x = v0 + r2.x; o.y = v1 + r2.y;
                    *reinterpret_cast<float2*>(C + (size_t)r * ncols + cg) = o;
                } else if (MODE == 2) {
                    __half* C = (__half*)Cv;
                    float o0 = 0.5f * v0 * (1.0f + erff(v0 * 0.70710678118654752f));
                    float o1 = 0.5f * v1 * (1.0f + erff(v1 * 0.70710678118654752f));
                    *reinterpret_cast<__half2*>(C + (size_t)r * ncols + cg) = __floats2half2_rn(o0, o1);
                } else {
                    float* C = (float*)Cv;
                    const float* rp = res + (size_t)r * ncols + cg;
                    float2 r2 = *reinterpret_cast<const float2*>(rp);
                    float2 o; o.x = (v0 + r2.x) * mr; o.y = (v1 + r2.y) * mr;
                    *reinterpret_cast<float2*>(C + (size_t)r * ncols + cg) = o;
                }
            }
        }
    }
}

// ======================= fused attention (unchanged from R7) ====================
#define FA_SMEM 49408

__global__ void __launch_bounds__(256, 2) attn_fused(
    const __half* __restrict__ Q, const __half* __restrict__ Kh,
    const __half* __restrict__ VT, const float* __restrict__ ebias,
    const uint8_t* __restrict__ adjm, __half* __restrict__ O)
{
    extern __shared__ char sm[];
    char*  Qs  = sm;
    char*  Ks  = sm + 16384;
    char*  Vs  = sm + 32768;
    float* lut = (float*)(sm + 49152);

    const int tid = threadIdx.x, lane = tid & 31, w = tid >> 5;
    const int lq = lane >> 2, lr = lane & 3;
    const int bh = blockIdx.y, b = bh >> 3, h = bh & 7;
    const int qt = blockIdx.x * 128;
    const int sl = swz3(lq);

    #pragma unroll
    for (int i = 0; i < 4; i++) {
        int idx = tid + i * 256, row = idx >> 3, g = idx & 7;
        cp16h(Qs + row * 128 + ((g ^ swz3(row & 7)) << 4),
              Q + ((size_t)bh * Nn + qt + row) * HDm + g * 8);
    }
    #pragma unroll
    for (int i = 0; i < 2; i++) {
        int idx = tid + i * 256, row = idx >> 3, g = idx & 7;
        int gp = ((g ^ swz3(row & 7)) << 4);
        cp16h(Ks + row * 128 + gp, Kh + ((size_t)bh * Nn + row) * HDm + g * 8);
        cp16h(Vs + row * 128 + gp, VT + ((size_t)bh * HDm + row) * Nn + g * 8);
    }
    if (tid < 48) lut[tid] = (tid < 40) ? ebias[tid] : -60000.0f;
    CP_COMMIT();
    #pragma unroll
    for (int i = 0; i < 2; i++) {
        int idx = tid + i * 256, row = idx >> 3, g = idx & 7;
        int gp = ((g ^ swz3(row & 7)) << 4);
        cp16h(Ks + 8192 + row * 128 + gp, Kh + ((size_t)bh * Nn + 64 + row) * HDm + g * 8);
        cp16h(Vs + 8192 + row * 128 + gp, VT + ((size_t)bh * HDm + row) * Nn + 64 + g * 8);
    }
    CP_COMMIT();

    float Oa[8][4];
    #pragma unroll
    for (int i = 0; i < 8; i++)
        #pragma unroll
        for (int j = 0; j < 4; j++) Oa[i][j] = 0.0f;
    float m0 = -1e30f, m1 = -1e30f, l0 = 0.0f, l1 = 0.0f;

    const int q0 = qt + w * 16 + lq;
    const uint8_t* am0 = adjm + ((size_t)b * Nn + q0) * Nn;
    const uint8_t* am1 = am0 + (size_t)8 * Nn;

    for (int t = 0; t < 8; t++) {
        CP_WAIT(1);
        __syncthreads();
        const char* Kb = Ks + (t & 1) * 8192;
        const char* Vb = Vs + (t & 1) * 8192;

        float Sa[8][4];
        #pragma unroll
        for (int i = 0; i < 8; i++)
            #pragma unroll
            for (int j = 0; j < 4; j++) Sa[i][j] = 0.0f;
        #pragma unroll
        for (int sc = 0; sc < 2; sc++) {
            int go = ((sc * 4 + lr) ^ sl) << 4;
            uint4 A0 = *reinterpret_cast<const uint4*>(Qs + (w*16 + lq    ) * 128 + go);
            uint4 A1 = *reinterpret_cast<const uint4*>(Qs + (w*16 + lq + 8) * 128 + go);
            #pragma unroll
            for (int nt = 0; nt < 8; nt++) {
                uint4 Bv = *reinterpret_cast<const uint4*>(Kb + (nt*8 + lq) * 128 + go);
                mma16(Sa[nt], A0.x, A1.x, A0.y, A1.y, Bv.x, Bv.y);
                mma16(Sa[nt], A0.z, A1.z, A0.w, A1.w, Bv.z, Bv.w);
            }
        }

        int kbase = t * 64;
        #pragma unroll
        for (int nt = 0; nt < 8; nt++) {
            int kc = kbase + nt * 8 + 2 * lr;
            uchar2 e0 = *reinterpret_cast<const uchar2*>(am0 + kc);
            uchar2 e1 = *reinterpret_cast<const uchar2*>(am1 + kc);
            Sa[nt][0] += lut[e0.x + h];
            Sa[nt][1] += lut[e0.y + h];
            Sa[nt][2] += lut[e1.x + h];
            Sa[nt][3] += lut[e1.y + h];
        }

        float tm0 = -1e30f, tm1 = -1e30f;
        #pragma unroll
        for (int nt = 0; nt < 8; nt++) {
            tm0 = fmaxf(tm0, fmaxf(Sa[nt][0], Sa[nt][1]));
            tm1 = fmaxf(tm1, fmaxf(Sa[nt][2], Sa[nt][3]));
        }
        tm0 = fmaxf(tm0, __shfl_xor_sync(0xffffffffu, tm0, 1));
        tm0 = fmaxf(tm0, __shfl_xor_sync(0xffffffffu, tm0, 2));
        tm1 = fmaxf(tm1, __shfl_xor_sync(0xffffffffu, tm1, 1));
        tm1 = fmaxf(tm1, __shfl_xor_sync(0xffffffffu, tm1, 2));
        float nm0 = fmaxf(m0, tm0), nm1 = fmaxf(m1, tm1);
        float c0 = expf(m0 - nm0), c1 = expf(m1 - nm1);
        float rs0 = 0.0f, rs1 = 0.0f;
        #pragma unroll
        for (int nt = 0; nt < 8; nt++) {
            Sa[nt][0] = expf(Sa[nt][0] - nm0); rs0 += Sa[nt][0];
            Sa[nt][1] = expf(Sa[nt][1] - nm0); rs0 += Sa[nt][1];
            Sa[nt][2] = expf(Sa[nt][2] - nm1); rs1 += Sa[nt][2];
            Sa[nt][3] = expf(Sa[nt][3] - nm1); rs1 += Sa[nt][3];
        }
        rs0 += __shfl_xor_sync(0xffffffffu, rs0, 1);
        rs0 += __shfl_xor_sync(0xffffffffu, rs0, 2);
        rs1 += __shfl_xor_sync(0xffffffffu, rs1, 1);
        rs1 += __shfl_xor_sync(0xffffffffu, rs1, 2);
        l0 = l0 * c0 + rs0; l1 = l1 * c1 + rs1;
        m0 = nm0; m1 = nm1;
        #pragma unroll
        for (int nt = 0; nt < 8; nt++) {
            Oa[nt][0] *= c0; Oa[nt][1] *= c0;
            Oa[nt][2] *= c1; Oa[nt][3] *= c1;
        }

        uint32_t ph[8][2];
        #pragma unroll
        for (int nt = 0; nt < 8; nt++) {
            ph[nt][0] = h2u(Sa[nt][0], Sa[nt][1]);
            ph[nt][1] = h2u(Sa[nt][2], Sa[nt][3]);
        }

        #pragma unroll
        for (int kf = 0; kf < 4; kf++) {
            uint32_t a0 = ph[2*kf][0],   a1 = ph[2*kf][1];
            uint32_t a2 = ph[2*kf+1][0], a3 = ph[2*kf+1][1];
            int g0 = (((2*kf)     ^ sl) << 4) + lr * 4;
            int g1 = (((2*kf + 1) ^ sl) << 4) + lr * 4;
            #pragma unroll
            for (int nt = 0; nt < 8; nt++) {
                const char* vr = Vb + (nt*8 + lq) * 128;
                uint32_t b0 = *reinterpret_cast<const uint32_t*>(vr + g0);
                uint32_t b1 = *reinterpret_cast<const uint32_t*>(vr + g1);
                mma16(Oa[nt], a0, a1, a2, a3, b0, b1);
            }
        }

        __syncthreads();
        if (t + 2 < 8) {
            int kt2 = (t + 2) * 64;
            char* dK = Ks + (t & 1) * 8192;
            char* dV = Vs + (t & 1) * 8192;
            #pragma unroll
            for (int i = 0; i < 2; i++) {
                int idx = tid + i * 256, row = idx >> 3, g = idx & 7;
                int gp = ((g ^ swz3(row & 7)) << 4);
                cp16h(dK + row * 128 + gp, Kh + ((size_t)bh * Nn + kt2 + row) * HDm + g * 8);
                cp16h(dV + row * 128 + gp, VT + ((size_t)bh * HDm + row) * Nn + kt2 + g * 8);
            }
        }
        CP_COMMIT();
    }

    float inv0 = (m0 > -5.0e4f) ? (1.0f / l0) : 0.0f;
    float inv1 = (m1 > -5.0e4f) ? (1.0f / l1) : 0.0f;
    __half* o0 = O + ((size_t)(b * Nn + q0)) * Dd + h * HDm;
    __half* o1 = o0 + (size_t)8 * Dd;
    #pragma unroll
    for (int nt = 0; nt < 8; nt++) {
        int d = nt * 8 + 2 * lr;
        *reinterpret_cast<__half2*>(o0 + d) = __floats2half2_rn(Oa[nt][0] * inv0, Oa[nt][1] * inv0);
        *reinterpret_cast<__half2*>(o1 + d) = __floats2half2_rn(Oa[nt][2] * inv1, Oa[nt][3] * inv1);
    }
}

// ---------------- adj pack ----------------
__global__ void adj_pack(const int* __restrict__ adj32, const float* __restrict__ mask,
                         uint8_t* __restrict__ out)
{
    const int is32 = g_adj_is32;
    int base = (blockIdx.x * 256 + threadIdx.x) * 8;
    int b = base >> 18;
    int rem = base & (Nn * Nn - 1);
    int q = rem >> 9;
    float mq = mask[b * Nn + q];
    const float* mkp = mask + b * Nn;
    int k0 = rem & 511;
    uchar4 o[2];
    #pragma unroll
    for (int e = 0; e < 8; e++) {
        int i = base + e;
        int t = is32 ? adj32[i] : adj32[2 * i];
        float mk = mkp[k0 + e];
        uint8_t v = (mq * mk == 0.0f) ? (uint8_t)40 : (uint8_t)(t << 3);
        ((uint8_t*)o)[e] = v;
    }
    *reinterpret_cast<uchar4*>(out + base)     = o[0];
    *reinterpret_cast<uchar4*>(out + base + 4) = o[1];
}

// ---------------- V transpose per (b,h) ----------------
__global__ void vtrans(const __half* __restrict__ V, __half* __restrict__ VT)
{
    __shared__ __half t[64][65];
    int bh = blockIdx.y, nb = blockIdx.x * 64;
    int tx = threadIdx.x, ty = threadIdx.y;
    const __half2* src = reinterpret_cast<const __half2*>(V + ((size_t)bh*Nn + nb) * HDm);
    #pragma unroll
    for (int i = 0; i < 8; i++) {
        int n = ty + i * 8;
        __half2 v = src[n * 32 + tx];
        t[n][2*tx] = __low2half(v); t[n][2*tx+1] = __high2half(v);
    }
    __syncthreads();
    __half2* dst = reinterpret_cast<__half2*>(VT + (size_t)bh * HDm * Nn);
    #pragma unroll
    for (int i = 0; i < 8; i++) {
        int d = ty + i * 8;
        __half2 o = __halves2half2(t[2*tx][d], t[2*tx+1][d]);
        dst[(d * Nn + nb + 2*tx) >> 1] = o;
    }
}

// ---------------- weight convert (all 6) ----------------
__global__ void wcvt6(const float* __restrict__ Wq, const float* __restrict__ Wk,
                      const float* __restrict__ Wv, const float* __restrict__ Wo,
                      const float* __restrict__ W1, const float* __restrict__ W2,
                      __half* __restrict__ dqkv, __half* __restrict__ dwo,
                      __half* __restrict__ dw1, __half* __restrict__ dw2)
{
    int z = blockIdx.z;
    const float* in; __half* out; int K, N;
    switch (z) {
        case 0: in = Wq; out = dqkv;                     K = Dd;  N = Dd;  break;
        case 1: in = Wk; out = dqkv + (size_t)Dd*Dd;     K = Dd;  N = Dd;  break;
        case 2: in = Wv; out = dqkv + (size_t)2*Dd*Dd;   K = Dd;  N = Dd;  break;
        case 3: in = Wo; out = dwo;                      K = Dd;  N = Dd;  break;
        case 4: in = W1; out = dw1;                      K = Dd;  N = DFF; break;
        default: in = W2; out = dw2;                     K = DFF; N = Dd;  break;
    }
    int bx = blockIdx.x * 32, by = blockIdx.y * 32;
    if (bx >= N || by >= K) return;
    __shared__ float t[32][33];
    int tx = threadIdx.x, ty = threadIdx.y;
    #pragma unroll
    for (int i = 0; i < 32; i += 8)
        t[ty + i][tx] = in[(size_t)(by + ty + i) * N + bx + tx];
    __syncthreads();
    #pragma unroll
    for (int i = 0; i < 32; i += 8)
        out[(size_t)(bx + ty + i) * K + by + tx] = __float2half_rn(t[tx][ty + i]);
}

// ---------------- prep: adj dtype detect + bias concat ----------------
__global__ void prep_kernel(const int* __restrict__ a,
                            const float* __restrict__ bq, const float* __restrict__ bk,
                            const float* __restrict__ bv, float* __restrict__ o)
{
    if (blockIdx.x == 0) {
        __shared__ int flag;
        if (threadIdx.x == 0) flag = 0;
        __syncthreads();
        for (int i = threadIdx.x; i < 8192; i += blockDim.x)
            if (a[2*i + 1] != 0) flag = 1;
        __syncthreads();
        if (threadIdx.x == 0) g_adj_is32 = flag;
    } else {
        int i = (blockIdx.x - 1) * 256 + threadIdx.x;
        if (i < 512) o[i] = bq[i];
        else if (i < 1024) o[i] = bk[i - 512];
        else o[i] = bv[i - 1024];
    }
}

// ---------------- LayerNorm: fp32 in, half out ----------------
__global__ __launch_bounds__(256) void ln_kernel(
    const float* __restrict__ X, const float* __restrict__ g,
    const float* __restrict__ beta, __half* __restrict__ Y)
{
    int row = blockIdx.x;
    const float* x = X + (size_t)row * Dd;
    int tid = threadIdx.x;
    float v0 = x[tid], v1 = x[tid + 256];

    __shared__ float red1[8], red2[8];
    float s = v0 + v1;
    #pragma unroll
    for (int o = 16; o; o >>= 1) s += __shfl_xor_sync(0xffffffffu, s, o);
    if ((tid & 31) == 0) red1[tid >> 5] = s;
    __syncthreads();
    float tot = red1[0]+red1[1]+red1[2]+red1[3]+red1[4]+red1[5]+red1[6]+red1[7];
    float mu = tot * (1.0f / 512.0f);

    float d0 = v0 - mu, d1 = v1 - mu;
    float s2 = d0*d0 + d1*d1;
    #pragma unroll
    for (int o = 16; o; o >>= 1) s2 += __shfl_xor_sync(0xffffffffu, s2, o);
    if ((tid & 31) == 0) red2[tid >> 5] = s2;
    __syncthreads();
    float tot2 = red2[0]+red2[1]+red2[2]+red2[3]+red2[4]+red2[5]+red2[6]+red2[7];
    float inv = rsqrtf(tot2 * (1.0f / 512.0f) + 1e-5f);

    Y[(size_t)row*Dd + tid      ] = __float2half_rn(d0 * inv * g[tid      ] + beta[tid      ]);
    Y[(size_t)row*Dd + tid + 256] = __float2half_rn(d1 * inv * g[tid + 256] + beta[tid + 256]);
}

// ---------------------------------- launch ----------------------------------
extern "C" void kernel_launch(void* const* d_in, const int* in_sizes, int n_in,
                              void* d_out, int out_size)
{
    const float* x    = (const float*)d_in[0];
    const int*   adj  = (const int*)  d_in[1];
    const float* mask = (const float*)d_in[2];
    const float* Wq   = (const float*)d_in[3];
    const float* bq   = (const float*)d_in[4];
    const float* Wk   = (const float*)d_in[5];
    const float* bk   = (const float*)d_in[6];
    const float* Wv   = (const float*)d_in[7];
    const float* bv   = (const float*)d_in[8];
    const float* Wo   = (const float*)d_in[9];
    const float* bo   = (const float*)d_in[10];
    const float* eb   = (const float*)d_in[11];
    const float* W1   = (const float*)d_in[12];
    const float* b1   = (const float*)d_in[13];
    const float* W2   = (const float*)d_in[14];
    const float* b2   = (const float*)d_in[15];
    const float* g1   = (const float*)d_in[16];
    const float* be1  = (const float*)d_in[17];
    const float* g2   = (const float*)d_in[18];
    const float* be2  = (const float*)d_in[19];
    float* out = (float*)d_out;

    __half *h1, *QKh, *Vh, *VTh, *O, *h2, *mid;
    __half *Wqkvh, *WoTh, *W1Th, *W2Th;
    float *x1, *bqkv;
    uint8_t* adjm;
    cudaGetSymbolAddress((void**)&h1,   g_h1);
    cudaGetSymbolAddress((void**)&QKh,  g_QKh);
    cudaGetSymbolAddress((void**)&Vh,   g_Vh);
    cudaGetSymbolAddress((void**)&VTh,  g_VTh);
    cudaGetSymbolAddress((void**)&O,    g_O);
    cudaGetSymbolAddress((void**)&x1,   g_x1);
    cudaGetSymbolAddress((void**)&h2,   g_h2);
    cudaGetSymbolAddress((void**)&mid,  g_mid);
    cudaGetSymbolAddress((void**)&Wqkvh,g_Wqkvh);
    cudaGetSymbolAddress((void**)&WoTh, g_WoTh);
    cudaGetSymbolAddress((void**)&W1Th, g_W1Th);
    cudaGetSymbolAddress((void**)&W2Th, g_W2Th);
    cudaGetSymbolAddress((void**)&bqkv, g_bqkv);
    cudaGetSymbolAddress((void**)&adjm, g_adjm);

    static int attr_set = 0;
    if (!attr_set) {
        cudaFuncSetAttribute(hgemm<0>, cudaFuncAttributeMaxDynamicSharedMemorySize, DENSE_SMEM);
        cudaFuncSetAttribute(hgemm<1>, cudaFuncAttributeMaxDynamicSharedMemorySize, DENSE_SMEM);
        cudaFuncSetAttribute(hgemm<2>, cudaFuncAttributeMaxDynamicSharedMemorySize, DENSE_SMEM);
        cudaFuncSetAttribute(hgemm<3>, cudaFuncAttributeMaxDynamicSharedMemorySize, DENSE_SMEM);
        cudaFuncSetAttribute(attn_fused, cudaFuncAttributeMaxDynamicSharedMemorySize, FA_SMEM);
        attr_set = 1;
    }

    dim3 tb(32, 8);
    // 0: prep (detect + bias concat)
    prep_kernel<<<7, 256>>>(adj, bq, bk, bv, bqkv);
    // 1: all weight converts
    wcvt6<<<dim3(64, 64, 6), tb>>>(Wq, Wk, Wv, Wo, W1, W2, Wqkvh, WoTh, W1Th, W2Th);
    // 2: LN1
    ln_kernel<<<MR, 256>>>(x, g1, be1, h1);
    // 3: fused QKV (profiled at capture index 3)
    hgemm<0><<<dim3(12, 64), 128, DENSE_SMEM>>>(h1, Wqkvh, bqkv, nullptr, nullptr, QKh, Dd, 3*Dd);
    // 4: adj pack
    adj_pack<<<(Bb*Nn*Nn)/(256*8), 256>>>(adj, mask, adjm);
    // 5: V transpose
    vtrans<<<dim3(8, Bb*Hh), tb>>>(Vh, VTh);
    // 6: fused attention
    const __half* Qp = QKh;
    const __half* Kp = QKh + (size_t)MR * Dd;
    attn_fused<<<dim3(4, Bb*Hh), 256, FA_SMEM>>>(Qp, Kp, VTh, eb, adjm, O);
    // 7: output projection + residual
    hgemm<1><<<dim3(4, 64), 128, DENSE_SMEM>>>(O, WoTh, bo, x, nullptr, x1, Dd, Dd);
    // 8: LN2
    ln_kernel<<<MR, 256>>>(x1, g2, be2, h2);
    // 9: FFN1 + gelu
    hgemm<2><<<dim3(16, 64), 128, DENSE_SMEM>>>(h2, W1Th, b1, nullptr, nullptr, mid, Dd, DFF);
    // 10: FFN2 + residual + mask
    hgemm<3><<<dim3(4, 64), 128, DENSE_SMEM>>>(mid, W2Th, b2, x1, mask, out, DFF, Dd);
}

// round 9
// speedup vs baseline: 1.0078x; 1.0078x over previous
#include <cuda_runtime.h>
#include <cuda_fp16.h>
#include <math.h>
#include <stdint.h>

#define Bb   16
#define Nn   512
#define Dd   512
#define Hh   8
#define HDm  64
#define MR   (Bb*Nn)
#define DFF  2048

// ---------------- scratch (static device globals) ----------------
__device__ __half g_h1 [MR*Dd];
__device__ __half g_QKh[2*MR*Dd];     // [2][B][H][N][HD]
__device__ __half g_Vh [MR*Dd];       // [B][H][N][HD]
__device__ __half g_VTh[MR*Dd];       // [B][H][HD][N]
__device__ __half g_O  [MR*Dd];       // (B,N,D) half
__device__ float  g_x1 [MR*Dd];
__device__ __half g_h2 [MR*Dd];
__device__ __half g_mid[MR*DFF];
__device__ __half g_Wqkvh[3*Dd*Dd];   // [1536][512] K-major
__device__ __half g_WoTh [Dd*Dd];
__device__ __half g_W1Th [DFF*Dd];
__device__ __half g_W2Th [Dd*DFF];
__device__ float  g_bqkv[3*Dd];
__device__ uint8_t g_adjm[(size_t)Bb*Nn*Nn];  // adj*8 or 40 (masked)
__device__ int    g_adj_is32;

// ======================= helpers =======================
__device__ __forceinline__ uint32_t smem_u32(const void* p) {
    uint32_t a;
    asm("{ .reg .u64 t; cvta.to.shared.u64 t, %1; cvt.u32.u64 %0, t; }" : "=r"(a) : "l"(p));
    return a;
}
__device__ __forceinline__ void cp16h(void* s, const __half* g) {
    uint32_t sa = smem_u32(s);
    asm volatile("cp.async.cg.shared.global [%0], [%1], 16;" :: "r"(sa), "l"(g) : "memory");
}
#define CP_COMMIT() asm volatile("cp.async.commit_group;" ::: "memory")
#define CP_WAIT(n)  asm volatile("cp.async.wait_group %0;" :: "n"(n) : "memory")

__device__ __forceinline__ int swz3(int r) {          // bit-reverse of r&7
    return ((r & 1) << 2) | (r & 2) | ((r & 4) >> 2);
}
__device__ __forceinline__ uint32_t h2u(float a, float b) {
    __half2 v = __floats2half2_rn(a, b);
    return *reinterpret_cast<uint32_t*>(&v);
}

// m16n8k16 fp16 mma, f32 accum, row.col
__device__ __forceinline__ void mma16(float* c, uint32_t a0, uint32_t a1, uint32_t a2,
                                      uint32_t a3, uint32_t b0, uint32_t b1) {
    asm volatile("mma.sync.aligned.m16n8k16.row.col.f32.f16.f16.f32 "
        "{%0,%1,%2,%3},{%4,%5,%6,%7},{%8,%9},{%0,%1,%2,%3};"
        : "+f"(c[0]), "+f"(c[1]), "+f"(c[2]), "+f"(c[3])
        : "r"(a0), "r"(a1), "r"(a2), "r"(a3), "r"(b0), "r"(b1));
}

// warp 32x64 tile compute over one 64-k plane pair (A rows at pa, B rows at pb)
__device__ __forceinline__ void plane_mma(const char* pa, const char* pb,
                                          float acc[2][8][4], int lq, int lr, int sl)
{
    #pragma unroll
    for (int sc = 0; sc < 2; sc++) {
        int go = ((sc * 4 + lr) ^ sl) << 4;
        uint4 Ar[2][2];
        #pragma unroll
        for (int mt = 0; mt < 2; mt++) {
            Ar[mt][0] = *reinterpret_cast<const uint4*>(pa + (mt*16 + lq    ) * 128 + go);
            Ar[mt][1] = *reinterpret_cast<const uint4*>(pa + (mt*16 + lq + 8) * 128 + go);
        }
        #pragma unroll
        for (int nt = 0; nt < 8; nt++) {
            uint4 Bv = *reinterpret_cast<const uint4*>(pb + (nt*8 + lq) * 128 + go);
            mma16(acc[0][nt], Ar[0][0].x, Ar[0][1].x, Ar[0][0].y, Ar[0][1].y, Bv.x, Bv.y);
            mma16(acc[1][nt], Ar[1][0].x, Ar[1][1].x, Ar[1][0].y, Ar[1][1].y, Bv.x, Bv.y);
            mma16(acc[0][nt], Ar[0][0].z, Ar[0][1].z, Ar[0][0].w, Ar[0][1].w, Bv.z, Bv.w);
            mma16(acc[1][nt], Ar[1][0].z, Ar[1][1].z, Ar[1][0].w, Ar[1][1].w, Bv.z, Bv.w);
        }
    }
}

// ======================= dense GEMM: CTA 128x128, 8 warps (32x64 each) ==========
// 3-stage cp.async pipeline, ONE __syncthreads per K-chunk.
#define DENSE_SMEM 98304

template<int MODE>
__global__ void __launch_bounds__(256, 2) hgemm(
    const __half* __restrict__ A, const __half* __restrict__ Wt,
    const float* __restrict__ bias, const float* __restrict__ res,
    const float* __restrict__ mask, void* Cv, int K, int ncols)
{
    extern __shared__ char sm[];
    const int tid = threadIdx.x, lane = tid & 31, warp = tid >> 5;
    const int wm = warp >> 1, wn = warp & 1, lq = lane >> 2, lr = lane & 3;
    const int bm = blockIdx.y * 128, bn = blockIdx.x * 128;
    const int sl = swz3(lq);

    float acc[2][8][4];
    #pragma unroll
    for (int i = 0; i < 2; i++)
        #pragma unroll
        for (int j = 0; j < 8; j++)
            #pragma unroll
            for (int l = 0; l < 4; l++) acc[i][j][l] = 0.0f;

    const int NC = K >> 6;

    auto loadc = [&](int c) {
        int buf = c % 3;
        char* dA = sm + buf * 32768;
        char* dB = dA + 16384;
        int k0 = c << 6;
        #pragma unroll
        for (int i = 0; i < 4; i++) {
            int idx = tid + i * 256, row = idx >> 3, g = idx & 7;
            int gp = ((g ^ swz3(row & 7)) << 4);
            cp16h(dA + row * 128 + gp, A  + (size_t)(bm + row) * K + k0 + g * 8);
            cp16h(dB + row * 128 + gp, Wt + (size_t)(bn + row) * K + k0 + g * 8);
        }
    };
    loadc(0); CP_COMMIT();
    loadc(1); CP_COMMIT();

    for (int c = 0; c < NC; c++) {
        CP_WAIT(1);
        __syncthreads();
        const char* base = sm + (c % 3) * 32768;
        plane_mma(base + (wm * 32) * 128, base + 16384 + (wn * 64) * 128, acc, lq, lr, sl);
        if (c + 2 < NC) loadc(c + 2);
        CP_COMMIT();
    }

    #pragma unroll
    for (int mt = 0; mt < 2; mt++) {
        #pragma unroll
        for (int hf = 0; hf < 2; hf++) {
            int r = bm + wm*32 + mt*16 + lq + hf*8;
            float mr = (MODE == 3) ? mask[r] : 0.0f;
            #pragma unroll
            for (int nt = 0; nt < 8; nt++) {
                int cg = bn + wn*64 + nt*8 + 2*lr;
                float v0 = acc[mt][nt][hf*2 + 0] + bias[cg];
                float v1 = acc[mt][nt][hf*2 + 1] + bias[cg + 1];
                if (MODE == 0) {
                    int mat = cg >> 9, cc = cg & 511, hh = cc >> 6, d0 = cc & 63;
                    int b = r >> 9, n = r & 511;
                    if (mat == 0) { v0 *= 0.125f; v1 *= 0.125f; }  // pre-scale Q
                    __half2 hv = __floats2half2_rn(v0, v1);
                    if (mat < 2) {
                        __half* op = (__half*)Cv + ((((size_t)mat*Bb + b)*Hh + hh)*Nn + n)*HDm + d0;
                        *reinterpret_cast<__half2*>(op) = hv;
                    } else {
                        __half* vp = g_Vh + (((size_t)b*Hh + hh)*Nn + n)*HDm + d0;
                        *reinterpret_cast<__half2*>(vp) = hv;
                    }
                } else if (MODE == 1) {
                    float* C = (float*)Cv;
                    const float* rp = res + (size_t)r * ncols + cg;
                    float2 r2 = *reinterpret_cast<const float2*>(rp);
                    float2 o; o.x = v0 + r2.x; o.y = v1 + r2.y;
                    *reinterpret_cast<float2*>(C + (size_t)r * ncols + cg) = o;
                } else if (MODE == 2) {
                    __half* C = (__half*)Cv;
                    float o0 = 0.5f * v0 * (1.0f + erff(v0 * 0.70710678118654752f));
                    float o1 = 0.5f * v1 * (1.0f + erff(v1 * 0.70710678118654752f));
                    *reinterpret_cast<__half2*>(C + (size_t)r * ncols + cg) = __floats2half2_rn(o0, o1);
                } else {
                    float* C = (float*)Cv;
                    const float* rp = res + (size_t)r * ncols + cg;
                    float2 r2 = *reinterpret_cast<const float2*>(rp);
                    float2 o; o.x = (v0 + r2.x) * mr; o.y = (v1 + r2.y) * mr;
                    *reinterpret_cast<float2*>(C + (size_t)r * ncols + cg) = o;
                }
            }
        }
    }
}

// ======================= fused attention (proven R7 version) ====================
#define FA_SMEM 49408

__global__ void __launch_bounds__(256, 2) attn_fused(
    const __half* __restrict__ Q, const __half* __restrict__ Kh,
    const __half* __restrict__ VT, const float* __restrict__ ebias,
    const uint8_t* __restrict__ adjm, __half* __restrict__ O)
{
    extern __shared__ char sm[];
    char*  Qs  = sm;
    char*  Ks  = sm + 16384;
    char*  Vs  = sm + 32768;
    float* lut = (float*)(sm + 49152);

    const int tid = threadIdx.x, lane = tid & 31, w = tid >> 5;
    const int lq = lane >> 2, lr = lane & 3;
    const int bh = blockIdx.y, b = bh >> 3, h = bh & 7;
    const int qt = blockIdx.x * 128;
    const int sl = swz3(lq);

    #pragma unroll
    for (int i = 0; i < 4; i++) {
        int idx = tid + i * 256, row = idx >> 3, g = idx & 7;
        cp16h(Qs + row * 128 + ((g ^ swz3(row & 7)) << 4),
              Q + ((size_t)bh * Nn + qt + row) * HDm + g * 8);
    }
    #pragma unroll
    for (int i = 0; i < 2; i++) {
        int idx = tid + i * 256, row = idx >> 3, g = idx & 7;
        int gp = ((g ^ swz3(row & 7)) << 4);
        cp16h(Ks + row * 128 + gp, Kh + ((size_t)bh * Nn + row) * HDm + g * 8);
        cp16h(Vs + row * 128 + gp, VT + ((size_t)bh * HDm + row) * Nn + g * 8);
    }
    if (tid < 48) lut[tid] = (tid < 40) ? ebias[tid] : -60000.0f;
    CP_COMMIT();
    #pragma unroll
    for (int i = 0; i < 2; i++) {
        int idx = tid + i * 256, row = idx >> 3, g = idx & 7;
        int gp = ((g ^ swz3(row & 7)) << 4);
        cp16h(Ks + 8192 + row * 128 + gp, Kh + ((size_t)bh * Nn + 64 + row) * HDm + g * 8);
        cp16h(Vs + 8192 + row * 128 + gp, VT + ((size_t)bh * HDm + row) * Nn + 64 + g * 8);
    }
    CP_COMMIT();

    float Oa[8][4];
    #pragma unroll
    for (int i = 0; i < 8; i++)
        #pragma unroll
        for (int j = 0; j < 4; j++) Oa[i][j] = 0.0f;
    float m0 = -1e30f, m1 = -1e30f, l0 = 0.0f, l1 = 0.0f;

    const int q0 = qt + w * 16 + lq;
    const uint8_t* am0 = adjm + ((size_t)b * Nn + q0) * Nn;
    const uint8_t* am1 = am0 + (size_t)8 * Nn;

    for (int t = 0; t < 8; t++) {
        CP_WAIT(1);
        __syncthreads();
        const char* Kb = Ks + (t & 1) * 8192;
        const char* Vb = Vs + (t & 1) * 8192;

        float Sa[8][4];
        #pragma unroll
        for (int i = 0; i < 8; i++)
            #pragma unroll
            for (int j = 0; j < 4; j++) Sa[i][j] = 0.0f;
        #pragma unroll
        for (int sc = 0; sc < 2; sc++) {
            int go = ((sc * 4 + lr) ^ sl) << 4;
            uint4 A0 = *reinterpret_cast<const uint4*>(Qs + (w*16 + lq    ) * 128 + go);
            uint4 A1 = *reinterpret_cast<const uint4*>(Qs + (w*16 + lq + 8) * 128 + go);
            #pragma unroll
            for (int nt = 0; nt < 8; nt++) {
                uint4 Bv = *reinterpret_cast<const uint4*>(Kb + (nt*8 + lq) * 128 + go);
                mma16(Sa[nt], A0.x, A1.x, A0.y, A1.y, Bv.x, Bv.y);
                mma16(Sa[nt], A0.z, A1.z, A0.w, A1.w, Bv.z, Bv.w);
            }
        }

        int kbase = t * 64;
        #pragma unroll
        for (int nt = 0; nt < 8; nt++) {
            int kc = kbase + nt * 8 + 2 * lr;
            uchar2 e0 = *reinterpret_cast<const uchar2*>(am0 + kc);
            uchar2 e1 = *reinterpret_cast<const uchar2*>(am1 + kc);
            Sa[nt][0] += lut[e0.x + h];
            Sa[nt][1] += lut[e0.y + h];
            Sa[nt][2] += lut[e1.x + h];
            Sa[nt][3] += lut[e1.y + h];
        }

        float tm0 = -1e30f, tm1 = -1e30f;
        #pragma unroll
        for (int nt = 0; nt < 8; nt++) {
            tm0 = fmaxf(tm0, fmaxf(Sa[nt][0], Sa[nt][1]));
            tm1 = fmaxf(tm1, fmaxf(Sa[nt][2], Sa[nt][3]));
        }
        tm0 = fmaxf(tm0, __shfl_xor_sync(0xffffffffu, tm0, 1));
        tm0 = fmaxf(tm0, __shfl_xor_sync(0xffffffffu, tm0, 2));
        tm1 = fmaxf(tm1, __shfl_xor_sync(0xffffffffu, tm1, 1));
        tm1 = fmaxf(tm1, __shfl_xor_sync(0xffffffffu, tm1, 2));
        float nm0 = fmaxf(m0, tm0), nm1 = fmaxf(m1, tm1);
        float c0 = expf(m0 - nm0), c1 = expf(m1 - nm1);
        float rs0 = 0.0f, rs1 = 0.0f;
        #pragma unroll
        for (int nt = 0; nt < 8; nt++) {
            Sa[nt][0] = expf(Sa[nt][0] - nm0); rs0 += Sa[nt][0];
            Sa[nt][1] = expf(Sa[nt][1] - nm0); rs0 += Sa[nt][1];
            Sa[nt][2] = expf(Sa[nt][2] - nm1); rs1 += Sa[nt][2];
            Sa[nt][3] = expf(Sa[nt][3] - nm1); rs1 += Sa[nt][3];
        }
        rs0 += __shfl_xor_sync(0xffffffffu, rs0, 1);
        rs0 += __shfl_xor_sync(0xffffffffu, rs0, 2);
        rs1 += __shfl_xor_sync(0xffffffffu, rs1, 1);
        rs1 += __shfl_xor_sync(0xffffffffu, rs1, 2);
        l0 = l0 * c0 + rs0; l1 = l1 * c1 + rs1;
        m0 = nm0; m1 = nm1;
        #pragma unroll
        for (int nt = 0; nt < 8; nt++) {
            Oa[nt][0] *= c0; Oa[nt][1] *= c0;
            Oa[nt][2] *= c1; Oa[nt][3] *= c1;
        }

        uint32_t ph[8][2];
        #pragma unroll
        for (int nt = 0; nt < 8; nt++) {
            ph[nt][0] = h2u(Sa[nt][0], Sa[nt][1]);
            ph[nt][1] = h2u(Sa[nt][2], Sa[nt][3]);
        }

        #pragma unroll
        for (int kf = 0; kf < 4; kf++) {
            uint32_t a0 = ph[2*kf][0],   a1 = ph[2*kf][1];
            uint32_t a2 = ph[2*kf+1][0], a3 = ph[2*kf+1][1];
            int g0 = (((2*kf)     ^ sl) << 4) + lr * 4;
            int g1 = (((2*kf + 1) ^ sl) << 4) + lr * 4;
            #pragma unroll
            for (int nt = 0; nt < 8; nt++) {
                const char* vr = Vb + (nt*8 + lq) * 128;
                uint32_t b0 = *reinterpret_cast<const uint32_t*>(vr + g0);
                uint32_t b1 = *reinterpret_cast<const uint32_t*>(vr + g1);
                mma16(Oa[nt], a0, a1, a2, a3, b0, b1);
            }
        }

        __syncthreads();
        if (t + 2 < 8) {
            int kt2 = (t + 2) * 64;
            char* dK = Ks + (t & 1) * 8192;
            char* dV = Vs + (t & 1) * 8192;
            #pragma unroll
            for (int i = 0; i < 2; i++) {
                int idx = tid + i * 256, row = idx >> 3, g = idx & 7;
                int gp = ((g ^ swz3(row & 7)) << 4);
                cp16h(dK + row * 128 + gp, Kh + ((size_t)bh * Nn + kt2 + row) * HDm + g * 8);
                cp16h(dV + row * 128 + gp, VT + ((size_t)bh * HDm + row) * Nn + kt2 + g * 8);
            }
        }
        CP_COMMIT();
    }

    float inv0 = (m0 > -5.0e4f) ? (1.0f / l0) : 0.0f;
    float inv1 = (m1 > -5.0e4f) ? (1.0f / l1) : 0.0f;
    __half* o0 = O + ((size_t)(b * Nn + q0)) * Dd + h * HDm;
    __half* o1 = o0 + (size_t)8 * Dd;
    #pragma unroll
    for (int nt = 0; nt < 8; nt++) {
        int d = nt * 8 + 2 * lr;
        *reinterpret_cast<__half2*>(o0 + d) = __floats2half2_rn(Oa[nt][0] * inv0, Oa[nt][1] * inv0);
        *reinterpret_cast<__half2*>(o1 + d) = __floats2half2_rn(Oa[nt][2] * inv1, Oa[nt][3] * inv1);
    }
}

// ---------------- adj pack ----------------
__global__ void adj_pack(const int* __restrict__ adj32, const float* __restrict__ mask,
                         uint8_t* __restrict__ out)
{
    const int is32 = g_adj_is32;
    int base = (blockIdx.x * 256 + threadIdx.x) * 8;
    int b = base >> 18;
    int rem = base & (Nn * Nn - 1);
    int q = rem >> 9;
    float mq = mask[b * Nn + q];
    const float* mkp = mask + b * Nn;
    int k0 = rem & 511;
    uchar4 o[2];
    #pragma unroll
    for (int e = 0; e < 8; e++) {
        int i = base + e;
        int t = is32 ? adj32[i] : adj32[2 * i];
        float mk = mkp[k0 + e];
        uint8_t v = (mq * mk == 0.0f) ? (uint8_t)40 : (uint8_t)(t << 3);
        ((uint8_t*)o)[e] = v;
    }
    *reinterpret_cast<uchar4*>(out + base)     = o[0];
    *reinterpret_cast<uchar4*>(out + base + 4) = o[1];
}

// ---------------- V transpose per (b,h) ----------------
__global__ void vtrans(const __half* __restrict__ V, __half* __restrict__ VT)
{
    __shared__ __half t[64][65];
    int bh = blockIdx.y, nb = blockIdx.x * 64;
    int tx = threadIdx.x, ty = threadIdx.y;
    const __half2* src = reinterpret_cast<const __half2*>(V + ((size_t)bh*Nn + nb) * HDm);
    #pragma unroll
    for (int i = 0; i < 8; i++) {
        int n = ty + i * 8;
        __half2 v = src[n * 32 + tx];
        t[n][2*tx] = __low2half(v); t[n][2*tx+1] = __high2half(v);
    }
    __syncthreads();
    __half2* dst = reinterpret_cast<__half2*>(VT + (size_t)bh * HDm * Nn);
    #pragma unroll
    for (int i = 0; i < 8; i++) {
        int d = ty + i * 8;
        __half2 o = __halves2half2(t[2*tx][d], t[2*tx+1][d]);
        dst[(d * Nn + nb + 2*tx) >> 1] = o;
    }
}

// ---------------- weight convert (all 6) ----------------
__global__ void wcvt6(const float* __restrict__ Wq, const float* __restrict__ Wk,
                      const float* __restrict__ Wv, const float* __restrict__ Wo,
                      const float* __restrict__ W1, const float* __restrict__ W2,
                      __half* __restrict__ dqkv, __half* __restrict__ dwo,
                      __half* __restrict__ dw1, __half* __restrict__ dw2)
{
    int z = blockIdx.z;
    const float* in; __half* out; int K, N;
    switch (z) {
        case 0: in = Wq; out = dqkv;                     K = Dd;  N = Dd;  break;
        case 1: in = Wk; out = dqkv + (size_t)Dd*Dd;     K = Dd;  N = Dd;  break;
        case 2: in = Wv; out = dqkv + (size_t)2*Dd*Dd;   K = Dd;  N = Dd;  break;
        case 3: in = Wo; out = dwo;                      K = Dd;  N = Dd;  break;
        case 4: in = W1; out = dw1;                      K = Dd;  N = DFF; break;
        default: in = W2; out = dw2;                     K = DFF; N = Dd;  break;
    }
    int bx = blockIdx.x * 32, by = blockIdx.y * 32;
    if (bx >= N || by >= K) return;
    __shared__ float t[32][33];
    int tx = threadIdx.x, ty = threadIdx.y;
    #pragma unroll
    for (int i = 0; i < 32; i += 8)
        t[ty + i][tx] = in[(size_t)(by + ty + i) * N + bx + tx];
    __syncthreads();
    #pragma unroll
    for (int i = 0; i < 32; i += 8)
        out[(size_t)(bx + ty + i) * K + by + tx] = __float2half_rn(t[tx][ty + i]);
}

// ---------------- prep: adj dtype detect + bias concat ----------------
__global__ void prep_kernel(const int* __restrict__ a,
                            const float* __restrict__ bq, const float* __restrict__ bk,
                            const float* __restrict__ bv, float* __restrict__ o)
{
    if (blockIdx.x == 0) {
        __shared__ int flag;
        if (threadIdx.x == 0) flag = 0;
        __syncthreads();
        for (int i = threadIdx.x; i < 8192; i += blockDim.x)
            if (a[2*i + 1] != 0) flag = 1;
        __syncthreads();
        if (threadIdx.x == 0) g_adj_is32 = flag;
    } else {
        int i = (blockIdx.x - 1) * 256 + threadIdx.x;
        if (i < 512) o[i] = bq[i];
        else if (i < 1024) o[i] = bk[i - 512];
        else o[i] = bv[i - 1024];
    }
}

// ---------------- LayerNorm: fp32 in, half out ----------------
__global__ __launch_bounds__(256) void ln_kernel(
    const float* __restrict__ X, const float* __restrict__ g,
    const float* __restrict__ beta, __half* __restrict__ Y)
{
    int row = blockIdx.x;
    const float* x = X + (size_t)row * Dd;
    int tid = threadIdx.x;
    float v0 = x[tid], v1 = x[tid + 256];

    __shared__ float red1[8], red2[8];
    float s = v0 + v1;
    #pragma unroll
    for (int o = 16; o; o >>= 1) s += __shfl_xor_sync(0xffffffffu, s, o);
    if ((tid & 31) == 0) red1[tid >> 5] = s;
    __syncthreads();
    float tot = red1[0]+red1[1]+red1[2]+red1[3]+red1[4]+red1[5]+red1[6]+red1[7];
    float mu = tot * (1.0f / 512.0f);

    float d0 = v0 - mu, d1 = v1 - mu;
    float s2 = d0*d0 + d1*d1;
    #pragma unroll
    for (int o = 16; o; o >>= 1) s2 += __shfl_xor_sync(0xffffffffu, s2, o);
    if ((tid & 31) == 0) red2[tid >> 5] = s2;
    __syncthreads();
    float tot2 = red2[0]+red2[1]+red2[2]+red2[3]+red2[4]+red2[5]+red2[6]+red2[7];
    float inv = rsqrtf(tot2 * (1.0f / 512.0f) + 1e-5f);

    Y[(size_t)row*Dd + tid      ] = __float2half_rn(d0 * inv * g[tid      ] + beta[tid      ]);
    Y[(size_t)row*Dd + tid + 256] = __float2half_rn(d1 * inv * g[tid + 256] + beta[tid + 256]);
}

// ---------------------------------- launch ----------------------------------
extern "C" void kernel_launch(void* const* d_in, const int* in_sizes, int n_in,
                              void* d_out, int out_size)
{
    const float* x    = (const float*)d_in[0];
    const int*   adj  = (const int*)  d_in[1];
    const float* mask = (const float*)d_in[2];
    const float* Wq   = (const float*)d_in[3];
    const float* bq   = (const float*)d_in[4];
    const float* Wk   = (const float*)d_in[5];
    const float* bk   = (const float*)d_in[6];
    const float* Wv   = (const float*)d_in[7];
    const float* bv   = (const float*)d_in[8];
    const float* Wo   = (const float*)d_in[9];
    const float* bo   = (const float*)d_in[10];
    const float* eb   = (const float*)d_in[11];
    const float* W1   = (const float*)d_in[12];
    const float* b1   = (const float*)d_in[13];
    const float* W2   = (const float*)d_in[14];
    const float* b2   = (const float*)d_in[15];
    const float* g1   = (const float*)d_in[16];
    const float* be1  = (const float*)d_in[17];
    const float* g2   = (const float*)d_in[18];
    const float* be2  = (const float*)d_in[19];
    float* out = (float*)d_out;

    __half *h1, *QKh, *Vh, *VTh, *O, *h2, *mid;
    __half *Wqkvh, *WoTh, *W1Th, *W2Th;
    float *x1, *bqkv;
    uint8_t* adjm;
    cudaGetSymbolAddress((void**)&h1,   g_h1);
    cudaGetSymbolAddress((void**)&QKh,  g_QKh);
    cudaGetSymbolAddress((void**)&Vh,   g_Vh);
    cudaGetSymbolAddress((void**)&VTh,  g_VTh);
    cudaGetSymbolAddress((void**)&O,    g_O);
    cudaGetSymbolAddress((void**)&x1,   g_x1);
    cudaGetSymbolAddress((void**)&h2,   g_h2);
    cudaGetSymbolAddress((void**)&mid,  g_mid);
    cudaGetSymbolAddress((void**)&Wqkvh,g_Wqkvh);
    cudaGetSymbolAddress((void**)&WoTh, g_WoTh);
    cudaGetSymbolAddress((void**)&W1Th, g_W1Th);
    cudaGetSymbolAddress((void**)&W2Th, g_W2Th);
    cudaGetSymbolAddress((void**)&bqkv, g_bqkv);
    cudaGetSymbolAddress((void**)&adjm, g_adjm);

    static int attr_set = 0;
    if (!attr_set) {
        cudaFuncSetAttribute(hgemm<0>, cudaFuncAttributeMaxDynamicSharedMemorySize, DENSE_SMEM);
        cudaFuncSetAttribute(hgemm<1>, cudaFuncAttributeMaxDynamicSharedMemorySize, DENSE_SMEM);
        cudaFuncSetAttribute(hgemm<2>, cudaFuncAttributeMaxDynamicSharedMemorySize, DENSE_SMEM);
        cudaFuncSetAttribute(hgemm<3>, cudaFuncAttributeMaxDynamicSharedMemorySize, DENSE_SMEM);
        cudaFuncSetAttribute(attn_fused, cudaFuncAttributeMaxDynamicSharedMemorySize, FA_SMEM);
        attr_set = 1;
    }

    dim3 tb(32, 8);
    // 0: prep (detect + bias concat)
    prep_kernel<<<7, 256>>>(adj, bq, bk, bv, bqkv);
    // 1: all weight converts
    wcvt6<<<dim3(64, 64, 6), tb>>>(Wq, Wk, Wv, Wo, W1, W2, Wqkvh, WoTh, W1Th, W2Th);
    // 2: LN1
    ln_kernel<<<MR, 256>>>(x, g1, be1, h1);
    // 3: fused QKV (profiled at capture index 3)
    hgemm<0><<<dim3(12, 64), 256, DENSE_SMEM>>>(h1, Wqkvh, bqkv, nullptr, nullptr, QKh, Dd, 3*Dd);
    // 4: adj pack
    adj_pack<<<(Bb*Nn*Nn)/(256*8), 256>>>(adj, mask, adjm);
    // 5: V transpose
    vtrans<<<dim3(8, Bb*Hh), tb>>>(Vh, VTh);
    // 6: fused attention
    const __half* Qp = QKh;
    const __half* Kp = QKh + (size_t)MR * Dd;
    attn_fused<<<dim3(4, Bb*Hh), 256, FA_SMEM>>>(Qp, Kp, VTh, eb, adjm, O);
    // 7: output projection + residual
    hgemm<1><<<dim3(4, 64), 256, DENSE_SMEM>>>(O, WoTh, bo, x, nullptr, x1, Dd, Dd);
    // 8: LN2
    ln_kernel<<<MR, 256>>>(x1, g2, be2, h2);
    // 9: FFN1 + gelu
    hgemm<2><<<dim3(16, 64), 256, DENSE_SMEM>>>(h2, W1Th, b1, nullptr, nullptr, mid, Dd, DFF);
    // 10: FFN2 + residual + mask
    hgemm<3><<<dim3(4, 64), 256, DENSE_SMEM>>>(mid, W2Th, b2, x1, mask, out, DFF, Dd);
}

// round 10
// speedup vs baseline: 1.0814x; 1.0731x over previous
#include <cuda_runtime.h>
#include <cuda_fp16.h>
#include <math.h>
#include <stdint.h>

#define Bb   16
#define Nn   512
#define Dd   512
#define Hh   8
#define HDm  64
#define MR   (Bb*Nn)
#define DFF  2048

// ---------------- scratch (static device globals) ----------------
__device__ __half g_h1 [MR*Dd];
__device__ __half g_QKh[2*MR*Dd];     // [2][B][H][N][HD]
__device__ __half g_Vh [MR*Dd];       // [B][H][N][HD]
__device__ __half g_VTh[MR*Dd];       // [B][H][HD][N]
__device__ __half g_O  [MR*Dd];       // (B,N,D) half
__device__ float  g_x1 [MR*Dd];
__device__ __half g_h2 [MR*Dd];
__device__ __half g_mid[MR*DFF];
__device__ __half g_Wqkvh[3*Dd*Dd];   // [1536][512] K-major
__device__ __half g_WoTh [Dd*Dd];
__device__ __half g_W1Th [DFF*Dd];
__device__ __half g_W2Th [Dd*DFF];
__device__ float  g_bqkv[3*Dd];
__device__ uint8_t g_adjm[(size_t)Bb*Nn*Nn];  // adj*8 or 40 (masked)
__device__ int    g_adj_is32;

#define LOG2E 1.44269504088896340736f

// ======================= helpers =======================
__device__ __forceinline__ uint32_t smem_u32(const void* p) {
    uint32_t a;
    asm("{ .reg .u64 t; cvta.to.shared.u64 t, %1; cvt.u32.u64 %0, t; }" : "=r"(a) : "l"(p));
    return a;
}
__device__ __forceinline__ void cp16h(void* s, const __half* g) {
    uint32_t sa = smem_u32(s);
    asm volatile("cp.async.cg.shared.global [%0], [%1], 16;" :: "r"(sa), "l"(g) : "memory");
}
#define CP_COMMIT() asm volatile("cp.async.commit_group;" ::: "memory")
#define CP_WAIT(n)  asm volatile("cp.async.wait_group %0;" :: "n"(n) : "memory")

__device__ __forceinline__ int swz3(int r) {          // bit-reverse of r&7
    return ((r & 1) << 2) | (r & 2) | ((r & 4) >> 2);
}
// exp2 of a packed pair: (a,b) -> half2(2^a, 2^b), returned as u32 fragment
__device__ __forceinline__ uint32_t ex2h2(float a, float b) {
    __half2 h = __floats2half2_rn(a, b);
    uint32_t u = *reinterpret_cast<uint32_t*>(&h);
    uint32_t r;
    asm("ex2.approx.f16x2 %0, %1;" : "=r"(r) : "r"(u));
    return r;
}

// m16n8k16 fp16 mma, f32 accum, row.col
__device__ __forceinline__ void mma16(float* c, uint32_t a0, uint32_t a1, uint32_t a2,
                                      uint32_t a3, uint32_t b0, uint32_t b1) {
    asm volatile("mma.sync.aligned.m16n8k16.row.col.f32.f16.f16.f32 "
        "{%0,%1,%2,%3},{%4,%5,%6,%7},{%8,%9},{%0,%1,%2,%3};"
        : "+f"(c[0]), "+f"(c[1]), "+f"(c[2]), "+f"(c[3])
        : "r"(a0), "r"(a1), "r"(a2), "r"(a3), "r"(b0), "r"(b1));
}

// warp 32x64 tile compute over one 64-k plane pair (A rows at pa, B rows at pb)
__device__ __forceinline__ void plane_mma(const char* pa, const char* pb,
                                          float acc[2][8][4], int lq, int lr, int sl)
{
    #pragma unroll
    for (int sc = 0; sc < 2; sc++) {
        int go = ((sc * 4 + lr) ^ sl) << 4;
        uint4 Ar[2][2];
        #pragma unroll
        for (int mt = 0; mt < 2; mt++) {
            Ar[mt][0] = *reinterpret_cast<const uint4*>(pa + (mt*16 + lq    ) * 128 + go);
            Ar[mt][1] = *reinterpret_cast<const uint4*>(pa + (mt*16 + lq + 8) * 128 + go);
        }
        #pragma unroll
        for (int nt = 0; nt < 8; nt++) {
            uint4 Bv = *reinterpret_cast<const uint4*>(pb + (nt*8 + lq) * 128 + go);
            mma16(acc[0][nt], Ar[0][0].x, Ar[0][1].x, Ar[0][0].y, Ar[0][1].y, Bv.x, Bv.y);
            mma16(acc[1][nt], Ar[1][0].x, Ar[1][1].x, Ar[1][0].y, Ar[1][1].y, Bv.x, Bv.y);
            mma16(acc[0][nt], Ar[0][0].z, Ar[0][1].z, Ar[0][0].w, Ar[0][1].w, Bv.z, Bv.w);
            mma16(acc[1][nt], Ar[1][0].z, Ar[1][1].z, Ar[1][0].w, Ar[1][1].w, Bv.z, Bv.w);
        }
    }
}

// ======================= dense GEMM: R7-proven 2-stage, 2-sync ==================
#define DENSE_SMEM 65536

template<int MODE>
__global__ void __launch_bounds__(256, 2) hgemm(
    const __half* __restrict__ A, const __half* __restrict__ Wt,
    const float* __restrict__ bias, const float* __restrict__ res,
    const float* __restrict__ mask, void* Cv, int K, int ncols)
{
    extern __shared__ char sm[];
    const int tid = threadIdx.x, lane = tid & 31, warp = tid >> 5;
    const int wm = warp >> 1, wn = warp & 1, lq = lane >> 2, lr = lane & 3;
    const int bm = blockIdx.y * 128, bn = blockIdx.x * 128;
    const int sl = swz3(lq);

    float acc[2][8][4];
    #pragma unroll
    for (int i = 0; i < 2; i++)
        #pragma unroll
        for (int j = 0; j < 8; j++)
            #pragma unroll
            for (int l = 0; l < 4; l++) acc[i][j][l] = 0.0f;

    const int NC = K >> 6;

    auto loadc = [&](int c, int buf) {
        char* dA = sm + buf * 32768;
        char* dB = dA + 16384;
        int k0 = c << 6;
        #pragma unroll
        for (int i = 0; i < 4; i++) {
            int idx = tid + i * 256, row = idx >> 3, g = idx & 7;
            int gp = ((g ^ swz3(row & 7)) << 4);
            cp16h(dA + row * 128 + gp, A  + (size_t)(bm + row) * K + k0 + g * 8);
            cp16h(dB + row * 128 + gp, Wt + (size_t)(bn + row) * K + k0 + g * 8);
        }
    };
    loadc(0, 0); CP_COMMIT();
    loadc(1, 1); CP_COMMIT();

    for (int c = 0; c < NC; c++) {
        CP_WAIT(1);
        __syncthreads();
        const char* pa = sm + (c & 1) * 32768 + (wm * 32) * 128;
        const char* pb = sm + (c & 1) * 32768 + 16384 + (wn * 64) * 128;
        plane_mma(pa, pb, acc, lq, lr, sl);
        __syncthreads();
        if (c + 2 < NC) loadc(c + 2, c & 1);
        CP_COMMIT();
    }

    #pragma unroll
    for (int mt = 0; mt < 2; mt++) {
        #pragma unroll
        for (int hf = 0; hf < 2; hf++) {
            int r = bm + wm*32 + mt*16 + lq + hf*8;
            float mr = (MODE == 3) ? mask[r] : 0.0f;
            #pragma unroll
            for (int nt = 0; nt < 8; nt++) {
                int cg = bn + wn*64 + nt*8 + 2*lr;
                float v0 = acc[mt][nt][hf*2 + 0] + bias[cg];
                float v1 = acc[mt][nt][hf*2 + 1] + bias[cg + 1];
                if (MODE == 0) {
                    int mat = cg >> 9, cc = cg & 511, hh = cc >> 6, d0 = cc & 63;
                    int b = r >> 9, n = r & 511;
                    // pre-scale Q by 0.125*log2(e): base-2 softmax domain
                    if (mat == 0) { v0 *= 0.125f*LOG2E; v1 *= 0.125f*LOG2E; }
                    __half2 hv = __floats2half2_rn(v0, v1);
                    if (mat < 2) {
                        __half* op = (__half*)Cv + ((((size_t)mat*Bb + b)*Hh + hh)*Nn + n)*HDm + d0;
                        *reinterpret_cast<__half2*>(op) = hv;
                    } else {
                        __half* vp = g_Vh + (((size_t)b*Hh + hh)*Nn + n)*HDm + d0;
                        *reinterpret_cast<__half2*>(vp) = hv;
                    }
                } else if (MODE == 1) {
                    float* C = (float*)Cv;
                    const float* rp = res + (size_t)r * ncols + cg;
                    float2 r2 = *reinterpret_cast<const float2*>(rp);
                    float2 o; o.x = v0 + r2.x; o.y = v1 + r2.y;
                    *reinterpret_cast<float2*>(C + (size_t)r * ncols + cg) = o;
                } else if (MODE == 2) {
                    __half* C = (__half*)Cv;
                    float o0 = 0.5f * v0 * (1.0f + erff(v0 * 0.70710678118654752f));
                    float o1 = 0.5f * v1 * (1.0f + erff(v1 * 0.70710678118654752f));
                    *reinterpret_cast<__half2*>(C + (size_t)r * ncols + cg) = __floats2half2_rn(o0, o1);
                } else {
                    float* C = (float*)Cv;
                    const float* rp = res + (size_t)r * ncols + cg;
                    float2 r2 = *reinterpret_cast<const float2*>(rp);
                    float2 o; o.x = (v0 + r2.x) * mr; o.y = (v1 + r2.y) * mr;
                    *reinterpret_cast<float2*>(C + (size_t)r * ncols + cg) = o;
                }
            }
        }
    }
}

// ======================= fused attention, base-2 softmax ========================
// S (base-2 domain) = Q'K + lut[t+h] where Q' = Q*0.125*log2e, lut = eb*log2e.
// Masked sentinel: -86562 (= -60000*log2e). exp via ex2.approx.f16x2.
#define FA_SMEM 49408

__global__ void __launch_bounds__(256, 2) attn_fused(
    const __half* __restrict__ Q, const __half* __restrict__ Kh,
    const __half* __restrict__ VT, const float* __restrict__ ebias,
    const uint8_t* __restrict__ adjm, __half* __restrict__ O)
{
    extern __shared__ char sm[];
    char*  Qs  = sm;
    char*  Ks  = sm + 16384;
    char*  Vs  = sm + 32768;
    float* lut = (float*)(sm + 49152);

    const int tid = threadIdx.x, lane = tid & 31, w = tid >> 5;
    const int lq = lane >> 2, lr = lane & 3;
    const int bh = blockIdx.y, b = bh >> 3, h = bh & 7;
    const int qt = blockIdx.x * 128;
    const int sl = swz3(lq);

    #pragma unroll
    for (int i = 0; i < 4; i++) {
        int idx = tid + i * 256, row = idx >> 3, g = idx & 7;
        cp16h(Qs + row * 128 + ((g ^ swz3(row & 7)) << 4),
              Q + ((size_t)bh * Nn + qt + row) * HDm + g * 8);
    }
    #pragma unroll
    for (int i = 0; i < 2; i++) {
        int idx = tid + i * 256, row = idx >> 3, g = idx & 7;
        int gp = ((g ^ swz3(row & 7)) << 4);
        cp16h(Ks + row * 128 + gp, Kh + ((size_t)bh * Nn + row) * HDm + g * 8);
        cp16h(Vs + row * 128 + gp, VT + ((size_t)bh * HDm + row) * Nn + g * 8);
    }
    if (tid < 48) lut[tid] = (tid < 40) ? (ebias[tid] * LOG2E) : -86561.7f;
    CP_COMMIT();
    #pragma unroll
    for (int i = 0; i < 2; i++) {
        int idx = tid + i * 256, row = idx >> 3, g = idx & 7;
        int gp = ((g ^ swz3(row & 7)) << 4);
        cp16h(Ks + 8192 + row * 128 + gp, Kh + ((size_t)bh * Nn + 64 + row) * HDm + g * 8);
        cp16h(Vs + 8192 + row * 128 + gp, VT + ((size_t)bh * HDm + row) * Nn + 64 + g * 8);
    }
    CP_COMMIT();

    float Oa[8][4];
    #pragma unroll
    for (int i = 0; i < 8; i++)
        #pragma unroll
        for (int j = 0; j < 4; j++) Oa[i][j] = 0.0f;
    float m0 = -1e30f, m1 = -1e30f, l0 = 0.0f, l1 = 0.0f;

    const int q0 = qt + w * 16 + lq;
    const uint8_t* am0 = adjm + ((size_t)b * Nn + q0) * Nn;
    const uint8_t* am1 = am0 + (size_t)8 * Nn;

    for (int t = 0; t < 8; t++) {
        CP_WAIT(1);
        __syncthreads();
        const char* Kb = Ks + (t & 1) * 8192;
        const char* Vb = Vs + (t & 1) * 8192;

        float Sa[8][4];
        #pragma unroll
        for (int i = 0; i < 8; i++)
            #pragma unroll
            for (int j = 0; j < 4; j++) Sa[i][j] = 0.0f;
        #pragma unroll
        for (int sc = 0; sc < 2; sc++) {
            int go = ((sc * 4 + lr) ^ sl) << 4;
            uint4 A0 = *reinterpret_cast<const uint4*>(Qs + (w*16 + lq    ) * 128 + go);
            uint4 A1 = *reinterpret_cast<const uint4*>(Qs + (w*16 + lq + 8) * 128 + go);
            #pragma unroll
            for (int nt = 0; nt < 8; nt++) {
                uint4 Bv = *reinterpret_cast<const uint4*>(Kb + (nt*8 + lq) * 128 + go);
                mma16(Sa[nt], A0.x, A1.x, A0.y, A1.y, Bv.x, Bv.y);
                mma16(Sa[nt], A0.z, A1.z, A0.w, A1.w, Bv.z, Bv.w);
            }
        }

        int kbase = t * 64;
        #pragma unroll
        for (int nt = 0; nt < 8; nt++) {
            int kc = kbase + nt * 8 + 2 * lr;
            uchar2 e0 = *reinterpret_cast<const uchar2*>(am0 + kc);
            uchar2 e1 = *reinterpret_cast<const uchar2*>(am1 + kc);
            Sa[nt][0] += lut[e0.x + h];
            Sa[nt][1] += lut[e0.y + h];
            Sa[nt][2] += lut[e1.x + h];
            Sa[nt][3] += lut[e1.y + h];
        }

        float tm0 = -1e30f, tm1 = -1e30f;
        #pragma unroll
        for (int nt = 0; nt < 8; nt++) {
            tm0 = fmaxf(tm0, fmaxf(Sa[nt][0], Sa[nt][1]));
            tm1 = fmaxf(tm1, fmaxf(Sa[nt][2], Sa[nt][3]));
        }
        tm0 = fmaxf(tm0, __shfl_xor_sync(0xffffffffu, tm0, 1));
        tm0 = fmaxf(tm0, __shfl_xor_sync(0xffffffffu, tm0, 2));
        tm1 = fmaxf(tm1, __shfl_xor_sync(0xffffffffu, tm1, 1));
        tm1 = fmaxf(tm1, __shfl_xor_sync(0xffffffffu, tm1, 2));
        float nm0 = fmaxf(m0, tm0), nm1 = fmaxf(m1, tm1);
        float c0 = exp2f(m0 - nm0), c1 = exp2f(m1 - nm1);

        // exp via f16x2 ex2: directly produces packed PV A-fragments
        uint32_t ph[8][2];
        float rs0 = 0.0f, rs1 = 0.0f;
        #pragma unroll
        for (int nt = 0; nt < 8; nt++) {
            ph[nt][0] = ex2h2(Sa[nt][0] - nm0, Sa[nt][1] - nm0);
            ph[nt][1] = ex2h2(Sa[nt][2] - nm1, Sa[nt][3] - nm1);
            float2 f0 = __half22float2(*reinterpret_cast<__half2*>(&ph[nt][0]));
            float2 f1 = __half22float2(*reinterpret_cast<__half2*>(&ph[nt][1]));
            rs0 += f0.x + f0.y;
            rs1 += f1.x + f1.y;
        }
        rs0 += __shfl_xor_sync(0xffffffffu, rs0, 1);
        rs0 += __shfl_xor_sync(0xffffffffu, rs0, 2);
        rs1 += __shfl_xor_sync(0xffffffffu, rs1, 1);
        rs1 += __shfl_xor_sync(0xffffffffu, rs1, 2);
        l0 = l0 * c0 + rs0; l1 = l1 * c1 + rs1;
        m0 = nm0; m1 = nm1;
        #pragma unroll
        for (int nt = 0; nt < 8; nt++) {
            Oa[nt][0] *= c0; Oa[nt][1] *= c0;
            Oa[nt][2] *= c1; Oa[nt][3] *= c1;
        }

        #pragma unroll
        for (int kf = 0; kf < 4; kf++) {
            uint32_t a0 = ph[2*kf][0],   a1 = ph[2*kf][1];
            uint32_t a2 = ph[2*kf+1][0], a3 = ph[2*kf+1][1];
            int g0 = (((2*kf)     ^ sl) << 4) + lr * 4;
            int g1 = (((2*kf + 1) ^ sl) << 4) + lr * 4;
            #pragma unroll
            for (int nt = 0; nt < 8; nt++) {
                const char* vr = Vb + (nt*8 + lq) * 128;
                uint32_t b0 = *reinterpret_cast<const uint32_t*>(vr + g0);
                uint32_t b1 = *reinterpret_cast<const uint32_t*>(vr + g1);
                mma16(Oa[nt], a0, a1, a2, a3, b0, b1);
            }
        }

        __syncthreads();
        if (t + 2 < 8) {
            int kt2 = (t + 2) * 64;
            char* dK = Ks + (t & 1) * 8192;
            char* dV = Vs + (t & 1) * 8192;
            #pragma unroll
            for (int i = 0; i < 2; i++) {
                int idx = tid + i * 256, row = idx >> 3, g = idx & 7;
                int gp = ((g ^ swz3(row & 7)) << 4);
                cp16h(dK + row * 128 + gp, Kh + ((size_t)bh * Nn + kt2 + row) * HDm + g * 8);
                cp16h(dV + row * 128 + gp, VT + ((size_t)bh * HDm + row) * Nn + kt2 + g * 8);
            }
        }
        CP_COMMIT();
    }

    float inv0 = (m0 > -7.0e4f) ? (1.0f / l0) : 0.0f;
    float inv1 = (m1 > -7.0e4f) ? (1.0f / l1) : 0.0f;
    __half* o0 = O + ((size_t)(b * Nn + q0)) * Dd + h * HDm;
    __half* o1 = o0 + (size_t)8 * Dd;
    #pragma unroll
    for (int nt = 0; nt < 8; nt++) {
        int d = nt * 8 + 2 * lr;
        *reinterpret_cast<__half2*>(o0 + d) = __floats2half2_rn(Oa[nt][0] * inv0, Oa[nt][1] * inv0);
        *reinterpret_cast<__half2*>(o1 + d) = __floats2half2_rn(Oa[nt][2] * inv1, Oa[nt][3] * inv1);
    }
}

// =============== mega-prep: detect+bias | LN1 rows | weight converts ============
__global__ void __launch_bounds__(256) prep_all(
    const int* __restrict__ adj,
    const float* __restrict__ bq, const float* __restrict__ bk,
    const float* __restrict__ bv, float* __restrict__ bqkv,
    const float* __restrict__ X, const float* __restrict__ g1,
    const float* __restrict__ be1, __half* __restrict__ Y,
    const float* __restrict__ Wq, const float* __restrict__ Wk,
    const float* __restrict__ Wv, const float* __restrict__ Wo,
    const float* __restrict__ W1, const float* __restrict__ W2,
    __half* __restrict__ dqkv, __half* __restrict__ dwo,
    __half* __restrict__ dw1, __half* __restrict__ dw2)
{
    const int bx = blockIdx.x, tid = threadIdx.x;
    if (bx == 0) {
        // adj dtype detect + bias concat
        __shared__ int flag;
        if (tid == 0) flag = 0;
        __syncthreads();
        for (int i = tid; i < 8192; i += 256)
            if (adj[2*i + 1] != 0) flag = 1;
        __syncthreads();
        if (tid == 0) g_adj_is32 = flag;
        for (int i = tid; i < 1536; i += 256)
            bqkv[i] = (i < 512) ? bq[i] : (i < 1024 ? bk[i - 512] : bv[i - 1024]);
        return;
    }
    if (bx <= MR) {
        // LayerNorm row
        int row = bx - 1;
        const float* x = X + (size_t)row * Dd;
        float v0 = x[tid], v1 = x[tid + 256];
        __shared__ float red1[8], red2[8];
        float s = v0 + v1;
        #pragma unroll
        for (int o = 16; o; o >>= 1) s += __shfl_xor_sync(0xffffffffu, s, o);
        if ((tid & 31) == 0) red1[tid >> 5] = s;
        __syncthreads();
        float tot = red1[0]+red1[1]+red1[2]+red1[3]+red1[4]+red1[5]+red1[6]+red1[7];
        float mu = tot * (1.0f / 512.0f);
        float d0 = v0 - mu, d1 = v1 - mu;
        float s2 = d0*d0 + d1*d1;
        #pragma unroll
        for (int o = 16; o; o >>= 1) s2 += __shfl_xor_sync(0xffffffffu, s2, o);
        if ((tid & 31) == 0) red2[tid >> 5] = s2;
        __syncthreads();
        float tot2 = red2[0]+red2[1]+red2[2]+red2[3]+red2[4]+red2[5]+red2[6]+red2[7];
        float inv = rsqrtf(tot2 * (1.0f / 512.0f) + 1e-5f);
        Y[(size_t)row*Dd + tid      ] = __float2half_rn(d0 * inv * g1[tid      ] + be1[tid      ]);
        Y[(size_t)row*Dd + tid + 256] = __float2half_rn(d1 * inv * g1[tid + 256] + be1[tid + 256]);
        return;
    }
    // weight convert tiles (round+transpose to K-major half)
    int t = bx - MR - 1;   // 0..3071
    const float* in; __half* out; int K, N, bxt, byt;
    if (t < 1024) {        // Wq/Wk/Wv/Wo: 256 tiles each (16x16)
        int z = t >> 8, r = t & 255;
        const float* srcs[4] = {Wq, Wk, Wv, Wo};
        __half* dsts[4] = {dqkv, dqkv + (size_t)Dd*Dd, dqkv + (size_t)2*Dd*Dd, dwo};
        in = srcs[z]; out = dsts[z]; K = Dd; N = Dd;
        bxt = (r & 15) * 32; byt = (r >> 4) * 32;
    } else if (t < 2048) { // W1: 64 x-tiles * 16 y-tiles
        int r = t - 1024;
        in = W1; out = dw1; K = Dd; N = DFF;
        bxt = (r & 63) * 32; byt = (r >> 6) * 32;
    } else {               // W2: 16 x-tiles * 64 y-tiles
        int r = t - 2048;
        in = W2; out = dw2; K = DFF; N = Dd;
        bxt = (r & 15) * 32; byt = (r >> 4) * 32;
    }
    __shared__ float tt[32][33];
    int tx = tid & 31, ty = tid >> 5;
    #pragma unroll
    for (int i = 0; i < 32; i += 8)
        tt[ty + i][tx] = in[(size_t)(byt + ty + i) * N + bxt + tx];
    __syncthreads();
    #pragma unroll
    for (int i = 0; i < 32; i += 8)
        out[(size_t)(bxt + ty + i) * K + byt + tx] = __float2half_rn(tt[tx][ty + i]);
}

// =============== pack+vtrans: adj pack | V transpose =============================
__global__ void __launch_bounds__(256) pack_vt(
    const int* __restrict__ adj32, const float* __restrict__ mask,
    uint8_t* __restrict__ out, const __half* __restrict__ V, __half* __restrict__ VT)
{
    const int bx = blockIdx.x, tid = threadIdx.x;
    if (bx < 2048) {
        // adj pack
        const int is32 = g_adj_is32;
        int base = (bx * 256 + tid) * 8;
        int b = base >> 18;
        int rem = base & (Nn * Nn - 1);
        int q = rem >> 9;
        float mq = mask[b * Nn + q];
        const float* mkp = mask + b * Nn;
        int k0 = rem & 511;
        uchar4 o[2];
        #pragma unroll
        for (int e = 0; e < 8; e++) {
            int i = base + e;
            int tv = is32 ? adj32[i] : adj32[2 * i];
            float mk = mkp[k0 + e];
            uint8_t v = (mq * mk == 0.0f) ? (uint8_t)40 : (uint8_t)(tv << 3);
            ((uint8_t*)o)[e] = v;
        }
        *reinterpret_cast<uchar4*>(out + base)     = o[0];
        *reinterpret_cast<uchar4*>(out + base + 4) = o[1];
        return;
    }
    // V transpose tile
    int t = bx - 2048;          // 0..1023
    int bh = t >> 3, nb = (t & 7) * 64;
    int tx = tid & 31, ty = tid >> 5;
    __shared__ __half tb[64][65];
    const __half2* src = reinterpret_cast<const __half2*>(V + ((size_t)bh*Nn + nb) * HDm);
    #pragma unroll
    for (int i = 0; i < 8; i++) {
        int n = ty + i * 8;
        __half2 v = src[n * 32 + tx];
        tb[n][2*tx] = __low2half(v); tb[n][2*tx+1] = __high2half(v);
    }
    __syncthreads();
    __half2* dst = reinterpret_cast<__half2*>(VT + (size_t)bh * HDm * Nn);
    #pragma unroll
    for (int i = 0; i < 8; i++) {
        int d = ty + i * 8;
        __half2 o = __halves2half2(tb[2*tx][d], tb[2*tx+1][d]);
        dst[(d * Nn + nb + 2*tx) >> 1] = o;
    }
}

// ---------------- LayerNorm (standalone, for LN2) ----------------
__global__ __launch_bounds__(256) void ln_kernel(
    const float* __restrict__ X, const float* __restrict__ g,
    const float* __restrict__ beta, __half* __restrict__ Y)
{
    int row = blockIdx.x;
    const float* x = X + (size_t)row * Dd;
    int tid = threadIdx.x;
    float v0 = x[tid], v1 = x[tid + 256];

    __shared__ float red1[8], red2[8];
    float s = v0 + v1;
    #pragma unroll
    for (int o = 16; o; o >>= 1) s += __shfl_xor_sync(0xffffffffu, s, o);
    if ((tid & 31) == 0) red1[tid >> 5] = s;
    __syncthreads();
    float tot = red1[0]+red1[1]+red1[2]+red1[3]+red1[4]+red1[5]+red1[6]+red1[7];
    float mu = tot * (1.0f / 512.0f);

    float d0 = v0 - mu, d1 = v1 - mu;
    float s2 = d0*d0 + d1*d1;
    #pragma unroll
    for (int o = 16; o; o >>= 1) s2 += __shfl_xor_sync(0xffffffffu, s2, o);
    if ((tid & 31) == 0) red2[tid >> 5] = s2;
    __syncthreads();
    float tot2 = red2[0]+red2[1]+red2[2]+red2[3]+red2[4]+red2[5]+red2[6]+red2[7];
    float inv = rsqrtf(tot2 * (1.0f / 512.0f) + 1e-5f);

    Y[(size_t)row*Dd + tid      ] = __float2half_rn(d0 * inv * g[tid      ] + beta[tid      ]);
    Y[(size_t)row*Dd + tid + 256] = __float2half_rn(d1 * inv * g[tid + 256] + beta[tid + 256]);
}

// ---------------------------------- launch ----------------------------------
extern "C" void kernel_launch(void* const* d_in, const int* in_sizes, int n_in,
                              void* d_out, int out_size)
{
    const float* x    = (const float*)d_in[0];
    const int*   adj  = (const int*)  d_in[1];
    const float* mask = (const float*)d_in[2];
    const float* Wq   = (const float*)d_in[3];
    const float* bq   = (const float*)d_in[4];
    const float* Wk   = (const float*)d_in[5];
    const float* bk   = (const float*)d_in[6];
    const float* Wv   = (const float*)d_in[7];
    const float* bv   = (const float*)d_in[8];
    const float* Wo   = (const float*)d_in[9];
    const float* bo   = (const float*)d_in[10];
    const float* eb   = (const float*)d_in[11];
    const float* W1   = (const float*)d_in[12];
    const float* b1   = (const float*)d_in[13];
    const float* W2   = (const float*)d_in[14];
    const float* b2   = (const float*)d_in[15];
    const float* g1   = (const float*)d_in[16];
    const float* be1  = (const float*)d_in[17];
    const float* g2   = (const float*)d_in[18];
    const float* be2  = (const float*)d_in[19];
    float* out = (float*)d_out;

    __half *h1, *QKh, *Vh, *VTh, *O, *h2, *mid;
    __half *Wqkvh, *WoTh, *W1Th, *W2Th;
    float *x1, *bqkv;
    uint8_t* adjm;
    cudaGetSymbolAddress((void**)&h1,   g_h1);
    cudaGetSymbolAddress((void**)&QKh,  g_QKh);
    cudaGetSymbolAddress((void**)&Vh,   g_Vh);
    cudaGetSymbolAddress((void**)&VTh,  g_VTh);
    cudaGetSymbolAddress((void**)&O,    g_O);
    cudaGetSymbolAddress((void**)&x1,   g_x1);
    cudaGetSymbolAddress((void**)&h2,   g_h2);
    cudaGetSymbolAddress((void**)&mid,  g_mid);
    cudaGetSymbolAddress((void**)&Wqkvh,g_Wqkvh);
    cudaGetSymbolAddress((void**)&WoTh, g_WoTh);
    cudaGetSymbolAddress((void**)&W1Th, g_W1Th);
    cudaGetSymbolAddress((void**)&W2Th, g_W2Th);
    cudaGetSymbolAddress((void**)&bqkv, g_bqkv);
    cudaGetSymbolAddress((void**)&adjm, g_adjm);

    static int attr_set = 0;
    if (!attr_set) {
        cudaFuncSetAttribute(hgemm<0>, cudaFuncAttributeMaxDynamicSharedMemorySize, DENSE_SMEM);
        cudaFuncSetAttribute(hgemm<1>, cudaFuncAttributeMaxDynamicSharedMemorySize, DENSE_SMEM);
        cudaFuncSetAttribute(hgemm<2>, cudaFuncAttributeMaxDynamicSharedMemorySize, DENSE_SMEM);
        cudaFuncSetAttribute(hgemm<3>, cudaFuncAttributeMaxDynamicSharedMemorySize, DENSE_SMEM);
        cudaFuncSetAttribute(attn_fused, cudaFuncAttributeMaxDynamicSharedMemorySize, FA_SMEM);
        attr_set = 1;
    }

    // 0: mega-prep (detect + bias + LN1 + all weight converts)
    prep_all<<<1 + MR + 3072, 256>>>(adj, bq, bk, bv, bqkv,
                                     x, g1, be1, h1,
                                     Wq, Wk, Wv, Wo, W1, W2,
                                     Wqkvh, WoTh, W1Th, W2Th);
    // 1: fused QKV
    hgemm<0><<<dim3(12, 64), 256, DENSE_SMEM>>>(h1, Wqkvh, bqkv, nullptr, nullptr, QKh, Dd, 3*Dd);
    // 2: adj pack + V transpose
    pack_vt<<<2048 + 1024, 256>>>(adj, mask, adjm, Vh, VTh);
    // 3: fused attention (profiled at capture index 3)
    const __half* Qp = QKh;
    const __half* Kp = QKh + (size_t)MR * Dd;
    attn_fused<<<dim3(4, Bb*Hh), 256, FA_SMEM>>>(Qp, Kp, VTh, eb, adjm, O);
    // 4: output projection + residual
    hgemm<1><<<dim3(4, 64), 256, DENSE_SMEM>>>(O, WoTh, bo, x, nullptr, x1, Dd, Dd);
    // 5: LN2
    ln_kernel<<<MR, 256>>>(x1, g2, be2, h2);
    // 6: FFN1 + gelu
    hgemm<2><<<dim3(16, 64), 256, DENSE_SMEM>>>(h2, W1Th, b1, nullptr, nullptr, mid, Dd, DFF);
    // 7: FFN2 + residual + mask
    hgemm<3><<<dim3(4, 64), 256, DENSE_SMEM>>>(mid, W2Th, b2, x1, mask, out, DFF, Dd);
}

// round 11
// speedup vs baseline: 1.0877x; 1.0058x over previous
#include <cuda_runtime.h>
#include <cuda_fp16.h>
#include <math.h>
#include <stdint.h>

#define Bb   16
#define Nn   512
#define Dd   512
#define Hh   8
#define HDm  64
#define MR   (Bb*Nn)
#define DFF  2048

// ---------------- scratch (static device globals) ----------------
__device__ __half g_h1 [MR*Dd];
__device__ __half g_QKh[2*MR*Dd];     // [2][B][H][N][HD]
__device__ __half g_Vh [MR*Dd];       // [B][H][N][HD]
__device__ __half g_VTf[MR*Dd];       // fragment-ordered V^T: [bh][d][ktile][32 words]
__device__ __half g_O  [MR*Dd];       // (B,N,D) half
__device__ float  g_x1 [MR*Dd];
__device__ __half g_h2 [MR*Dd];
__device__ __half g_mid[MR*DFF];
__device__ __half g_Wqkvh[3*Dd*Dd];   // [1536][512] K-major
__device__ __half g_WoTh [Dd*Dd];
__device__ __half g_W1Th [DFF*Dd];
__device__ __half g_W2Th [Dd*DFF];
__device__ float  g_bqkv[3*Dd];
__device__ uint8_t g_adjm[(size_t)Bb*Nn*Nn];  // adj*8 or 40 (masked)
__device__ int    g_adj_is32;

#define LOG2E 1.44269504088896340736f

// ======================= helpers =======================
__device__ __forceinline__ uint32_t smem_u32(const void* p) {
    uint32_t a;
    asm("{ .reg .u64 t; cvta.to.shared.u64 t, %1; cvt.u32.u64 %0, t; }" : "=r"(a) : "l"(p));
    return a;
}
__device__ __forceinline__ void cp16h(void* s, const __half* g) {
    uint32_t sa = smem_u32(s);
    asm volatile("cp.async.cg.shared.global [%0], [%1], 16;" :: "r"(sa), "l"(g) : "memory");
}
#define CP_COMMIT() asm volatile("cp.async.commit_group;" ::: "memory")
#define CP_WAIT(n)  asm volatile("cp.async.wait_group %0;" :: "n"(n) : "memory")

__device__ __forceinline__ int swz3(int r) {          // bit-reverse of r&7
    return ((r & 1) << 2) | (r & 2) | ((r & 4) >> 2);
}
// exp2 of a packed pair: (a,b) -> half2(2^a, 2^b), returned as u32 fragment
__device__ __forceinline__ uint32_t ex2h2(float a, float b) {
    __half2 h = __floats2half2_rn(a, b);
    uint32_t u = *reinterpret_cast<uint32_t*>(&h);
    uint32_t r;
    asm("ex2.approx.f16x2 %0, %1;" : "=r"(r) : "r"(u));
    return r;
}

// m16n8k16 fp16 mma, f32 accum, row.col
__device__ __forceinline__ void mma16(float* c, uint32_t a0, uint32_t a1, uint32_t a2,
                                      uint32_t a3, uint32_t b0, uint32_t b1) {
    asm volatile("mma.sync.aligned.m16n8k16.row.col.f32.f16.f16.f32 "
        "{%0,%1,%2,%3},{%4,%5,%6,%7},{%8,%9},{%0,%1,%2,%3};"
        : "+f"(c[0]), "+f"(c[1]), "+f"(c[2]), "+f"(c[3])
        : "r"(a0), "r"(a1), "r"(a2), "r"(a3), "r"(b0), "r"(b1));
}

// warp 32x64 tile compute over one 64-k plane pair (A rows at pa, B rows at pb)
__device__ __forceinline__ void plane_mma(const char* pa, const char* pb,
                                          float acc[2][8][4], int lq, int lr, int sl)
{
    #pragma unroll
    for (int sc = 0; sc < 2; sc++) {
        int go = ((sc * 4 + lr) ^ sl) << 4;
        uint4 Ar[2][2];
        #pragma unroll
        for (int mt = 0; mt < 2; mt++) {
            Ar[mt][0] = *reinterpret_cast<const uint4*>(pa + (mt*16 + lq    ) * 128 + go);
            Ar[mt][1] = *reinterpret_cast<const uint4*>(pa + (mt*16 + lq + 8) * 128 + go);
        }
        #pragma unroll
        for (int nt = 0; nt < 8; nt++) {
            uint4 Bv = *reinterpret_cast<const uint4*>(pb + (nt*8 + lq) * 128 + go);
            mma16(acc[0][nt], Ar[0][0].x, Ar[0][1].x, Ar[0][0].y, Ar[0][1].y, Bv.x, Bv.y);
            mma16(acc[1][nt], Ar[1][0].x, Ar[1][1].x, Ar[1][0].y, Ar[1][1].y, Bv.x, Bv.y);
            mma16(acc[0][nt], Ar[0][0].z, Ar[0][1].z, Ar[0][0].w, Ar[0][1].w, Bv.z, Bv.w);
            mma16(acc[1][nt], Ar[1][0].z, Ar[1][1].z, Ar[1][0].w, Ar[1][1].w, Bv.z, Bv.w);
        }
    }
}

// ======================= dense GEMM: R7-proven 2-stage, 2-sync ==================
#define DENSE_SMEM 65536

template<int MODE>
__global__ void __launch_bounds__(256, 2) hgemm(
    const __half* __restrict__ A, const __half* __restrict__ Wt,
    const float* __restrict__ bias, const float* __restrict__ res,
    const float* __restrict__ mask, void* Cv, int K, int ncols)
{
    extern __shared__ char sm[];
    const int tid = threadIdx.x, lane = tid & 31, warp = tid >> 5;
    const int wm = warp >> 1, wn = warp & 1, lq = lane >> 2, lr = lane & 3;
    const int bm = blockIdx.y * 128, bn = blockIdx.x * 128;
    const int sl = swz3(lq);

    float acc[2][8][4];
    #pragma unroll
    for (int i = 0; i < 2; i++)
        #pragma unroll
        for (int j = 0; j < 8; j++)
            #pragma unroll
            for (int l = 0; l < 4; l++) acc[i][j][l] = 0.0f;

    const int NC = K >> 6;

    auto loadc = [&](int c, int buf) {
        char* dA = sm + buf * 32768;
        char* dB = dA + 16384;
        int k0 = c << 6;
        #pragma unroll
        for (int i = 0; i < 4; i++) {
            int idx = tid + i * 256, row = idx >> 3, g = idx & 7;
            int gp = ((g ^ swz3(row & 7)) << 4);
            cp16h(dA + row * 128 + gp, A  + (size_t)(bm + row) * K + k0 + g * 8);
            cp16h(dB + row * 128 + gp, Wt + (size_t)(bn + row) * K + k0 + g * 8);
        }
    };
    loadc(0, 0); CP_COMMIT();
    loadc(1, 1); CP_COMMIT();

    for (int c = 0; c < NC; c++) {
        CP_WAIT(1);
        __syncthreads();
        const char* pa = sm + (c & 1) * 32768 + (wm * 32) * 128;
        const char* pb = sm + (c & 1) * 32768 + 16384 + (wn * 64) * 128;
        plane_mma(pa, pb, acc, lq, lr, sl);
        __syncthreads();
        if (c + 2 < NC) loadc(c + 2, c & 1);
        CP_COMMIT();
    }

    #pragma unroll
    for (int mt = 0; mt < 2; mt++) {
        #pragma unroll
        for (int hf = 0; hf < 2; hf++) {
            int r = bm + wm*32 + mt*16 + lq + hf*8;
            float mr = (MODE == 3) ? mask[r] : 0.0f;
            #pragma unroll
            for (int nt = 0; nt < 8; nt++) {
                int cg = bn + wn*64 + nt*8 + 2*lr;
                float v0 = acc[mt][nt][hf*2 + 0] + bias[cg];
                float v1 = acc[mt][nt][hf*2 + 1] + bias[cg + 1];
                if (MODE == 0) {
                    int mat = cg >> 9, cc = cg & 511, hh = cc >> 6, d0 = cc & 63;
                    int b = r >> 9, n = r & 511;
                    if (mat == 0) { v0 *= 0.125f*LOG2E; v1 *= 0.125f*LOG2E; }
                    __half2 hv = __floats2half2_rn(v0, v1);
                    if (mat < 2) {
                        __half* op = (__half*)Cv + ((((size_t)mat*Bb + b)*Hh + hh)*Nn + n)*HDm + d0;
                        *reinterpret_cast<__half2*>(op) = hv;
                    } else {
                        __half* vp = g_Vh + (((size_t)b*Hh + hh)*Nn + n)*HDm + d0;
                        *reinterpret_cast<__half2*>(vp) = hv;
                    }
                } else if (MODE == 1) {
                    float* C = (float*)Cv;
                    const float* rp = res + (size_t)r * ncols + cg;
                    float2 r2 = *reinterpret_cast<const float2*>(rp);
                    float2 o; o.x = v0 + r2.x; o.y = v1 + r2.y;
                    *reinterpret_cast<float2*>(C + (size_t)r * ncols + cg) = o;
                } else if (MODE == 2) {
                    __half* C = (__half*)Cv;
                    float o0 = 0.5f * v0 * (1.0f + erff(v0 * 0.70710678118654752f));
                    float o1 = 0.5f * v1 * (1.0f + erff(v1 * 0.70710678118654752f));
                    *reinterpret_cast<__half2*>(C + (size_t)r * ncols + cg) = __floats2half2_rn(o0, o1);
                } else {
                    float* C = (float*)Cv;
                    const float* rp = res + (size_t)r * ncols + cg;
                    float2 r2 = *reinterpret_cast<const float2*>(rp);
                    float2 o; o.x = (v0 + r2.x) * mr; o.y = (v1 + r2.y) * mr;
                    *reinterpret_cast<float2*>(C + (size_t)r * ncols + cg) = o;
                }
            }
        }
    }
}

// ======================= fused attention, base-2 softmax ========================
// V^T stored fragment-ordered: per (d,ktile) 128B row, word p = (lr*8+g)^((d&7)<<2)
// holds k = {8g+2lr, 8g+2lr+1}. PV B-frags load as uint4 (4-lane broadcast).
#define FA_SMEM 49408

__global__ void __launch_bounds__(256, 2) attn_fused(
    const __half* __restrict__ Q, const __half* __restrict__ Kh,
    const __half* __restrict__ VTf, const float* __restrict__ ebias,
    const uint8_t* __restrict__ adjm, __half* __restrict__ O)
{
    extern __shared__ char sm[];
    char*  Qs  = sm;
    char*  Ks  = sm + 16384;
    char*  Vs  = sm + 32768;
    float* lut = (float*)(sm + 49152);

    const int tid = threadIdx.x, lane = tid & 31, w = tid >> 5;
    const int lq = lane >> 2, lr = lane & 3;
    const int bh = blockIdx.y, b = bh >> 3, h = bh & 7;
    const int qt = blockIdx.x * 128;
    const int sl = swz3(lq);

    #pragma unroll
    for (int i = 0; i < 4; i++) {
        int idx = tid + i * 256, row = idx >> 3, g = idx & 7;
        cp16h(Qs + row * 128 + ((g ^ swz3(row & 7)) << 4),
              Q + ((size_t)bh * Nn + qt + row) * HDm + g * 8);
    }
    #pragma unroll
    for (int i = 0; i < 2; i++) {
        int idx = tid + i * 256, row = idx >> 3, g = idx & 7;
        int gp = ((g ^ swz3(row & 7)) << 4);
        cp16h(Ks + row * 128 + gp, Kh + ((size_t)bh * Nn + row) * HDm + g * 8);
        // V: identity 128B row copy from fragment-ordered global (ktile 0)
        cp16h(Vs + row * 128 + g * 16,
              VTf + (((size_t)bh * HDm + row) * 8 + 0) * 64 + g * 8);
    }
    if (tid < 48) lut[tid] = (tid < 40) ? (ebias[tid] * LOG2E) : -86561.7f;
    CP_COMMIT();
    #pragma unroll
    for (int i = 0; i < 2; i++) {
        int idx = tid + i * 256, row = idx >> 3, g = idx & 7;
        int gp = ((g ^ swz3(row & 7)) << 4);
        cp16h(Ks + 8192 + row * 128 + gp, Kh + ((size_t)bh * Nn + 64 + row) * HDm + g * 8);
        cp16h(Vs + 8192 + row * 128 + g * 16,
              VTf + (((size_t)bh * HDm + row) * 8 + 1) * 64 + g * 8);
    }
    CP_COMMIT();

    float Oa[8][4];
    #pragma unroll
    for (int i = 0; i < 8; i++)
        #pragma unroll
        for (int j = 0; j < 4; j++) Oa[i][j] = 0.0f;
    float m0 = -1e30f, m1 = -1e30f, l0 = 0.0f, l1 = 0.0f;

    const int q0 = qt + w * 16 + lq;
    const uint8_t* am0 = adjm + ((size_t)b * Nn + q0) * Nn;
    const uint8_t* am1 = am0 + (size_t)8 * Nn;
    const int xr = lq << 2;

    for (int t = 0; t < 8; t++) {
        CP_WAIT(1);
        __syncthreads();
        const char* Kb = Ks + (t & 1) * 8192;
        const char* Vb = Vs + (t & 1) * 8192;

        float Sa[8][4];
        #pragma unroll
        for (int i = 0; i < 8; i++)
            #pragma unroll
            for (int j = 0; j < 4; j++) Sa[i][j] = 0.0f;
        #pragma unroll
        for (int sc = 0; sc < 2; sc++) {
            int go = ((sc * 4 + lr) ^ sl) << 4;
            uint4 A0 = *reinterpret_cast<const uint4*>(Qs + (w*16 + lq    ) * 128 + go);
            uint4 A1 = *reinterpret_cast<const uint4*>(Qs + (w*16 + lq + 8) * 128 + go);
            #pragma unroll
            for (int nt = 0; nt < 8; nt++) {
                uint4 Bv = *reinterpret_cast<const uint4*>(Kb + (nt*8 + lq) * 128 + go);
                mma16(Sa[nt], A0.x, A1.x, A0.y, A1.y, Bv.x, Bv.y);
                mma16(Sa[nt], A0.z, A1.z, A0.w, A1.w, Bv.z, Bv.w);
            }
        }

        int kbase = t * 64;
        #pragma unroll
        for (int nt = 0; nt < 8; nt++) {
            int kc = kbase + nt * 8 + 2 * lr;
            uchar2 e0 = *reinterpret_cast<const uchar2*>(am0 + kc);
            uchar2 e1 = *reinterpret_cast<const uchar2*>(am1 + kc);
            Sa[nt][0] += lut[e0.x + h];
            Sa[nt][1] += lut[e0.y + h];
            Sa[nt][2] += lut[e1.x + h];
            Sa[nt][3] += lut[e1.y + h];
        }

        float tm0 = -1e30f, tm1 = -1e30f;
        #pragma unroll
        for (int nt = 0; nt < 8; nt++) {
            tm0 = fmaxf(tm0, fmaxf(Sa[nt][0], Sa[nt][1]));
            tm1 = fmaxf(tm1, fmaxf(Sa[nt][2], Sa[nt][3]));
        }
        tm0 = fmaxf(tm0, __shfl_xor_sync(0xffffffffu, tm0, 1));
        tm0 = fmaxf(tm0, __shfl_xor_sync(0xffffffffu, tm0, 2));
        tm1 = fmaxf(tm1, __shfl_xor_sync(0xffffffffu, tm1, 1));
        tm1 = fmaxf(tm1, __shfl_xor_sync(0xffffffffu, tm1, 2));
        float nm0 = fmaxf(m0, tm0), nm1 = fmaxf(m1, tm1);
        float c0 = exp2f(m0 - nm0), c1 = exp2f(m1 - nm1);

        uint32_t ph[8][2];
        float rs0 = 0.0f, rs1 = 0.0f;
        #pragma unroll
        for (int nt = 0; nt < 8; nt++) {
            ph[nt][0] = ex2h2(Sa[nt][0] - nm0, Sa[nt][1] - nm0);
            ph[nt][1] = ex2h2(Sa[nt][2] - nm1, Sa[nt][3] - nm1);
            float2 f0 = __half22float2(*reinterpret_cast<__half2*>(&ph[nt][0]));
            float2 f1 = __half22float2(*reinterpret_cast<__half2*>(&ph[nt][1]));
            rs0 += f0.x + f0.y;
            rs1 += f1.x + f1.y;
        }
        rs0 += __shfl_xor_sync(0xffffffffu, rs0, 1);
        rs0 += __shfl_xor_sync(0xffffffffu, rs0, 2);
        rs1 += __shfl_xor_sync(0xffffffffu, rs1, 1);
        rs1 += __shfl_xor_sync(0xffffffffu, rs1, 2);
        l0 = l0 * c0 + rs0; l1 = l1 * c1 + rs1;
        m0 = nm0; m1 = nm1;
        #pragma unroll
        for (int nt = 0; nt < 8; nt++) {
            Oa[nt][0] *= c0; Oa[nt][1] *= c0;
            Oa[nt][2] *= c1; Oa[nt][3] *= c1;
        }

        // PV mma: fragment-ordered V, 2x uint4 per nt (4-lane broadcast, no conflicts)
        #pragma unroll
        for (int nt = 0; nt < 8; nt++) {
            const char* vr = Vb + (nt*8 + lq) * 128;
            uint4 B0 = *reinterpret_cast<const uint4*>(vr + (((lr*8    ) ^ xr) << 2));
            uint4 B1 = *reinterpret_cast<const uint4*>(vr + (((lr*8 + 4) ^ xr) << 2));
            mma16(Oa[nt], ph[0][0], ph[0][1], ph[1][0], ph[1][1], B0.x, B0.y);
            mma16(Oa[nt], ph[2][0], ph[2][1], ph[3][0], ph[3][1], B0.z, B0.w);
            mma16(Oa[nt], ph[4][0], ph[4][1], ph[5][0], ph[5][1], B1.x, B1.y);
            mma16(Oa[nt], ph[6][0], ph[6][1], ph[7][0], ph[7][1], B1.z, B1.w);
        }

        __syncthreads();
        if (t + 2 < 8) {
            int kt2 = t + 2;
            char* dK = Ks + (t & 1) * 8192;
            char* dV = Vs + (t & 1) * 8192;
            #pragma unroll
            for (int i = 0; i < 2; i++) {
                int idx = tid + i * 256, row = idx >> 3, g = idx & 7;
                int gp = ((g ^ swz3(row & 7)) << 4);
                cp16h(dK + row * 128 + gp, Kh + ((size_t)bh * Nn + kt2*64 + row) * HDm + g * 8);
                cp16h(dV + row * 128 + g * 16,
                      VTf + (((size_t)bh * HDm + row) * 8 + kt2) * 64 + g * 8);
            }
        }
        CP_COMMIT();
    }

    float inv0 = (m0 > -7.0e4f) ? (1.0f / l0) : 0.0f;
    float inv1 = (m1 > -7.0e4f) ? (1.0f / l1) : 0.0f;
    __half* o0 = O + ((size_t)(b * Nn + q0)) * Dd + h * HDm;
    __half* o1 = o0 + (size_t)8 * Dd;
    #pragma unroll
    for (int nt = 0; nt < 8; nt++) {
        int d = nt * 8 + 2 * lr;
        *reinterpret_cast<__half2*>(o0 + d) = __floats2half2_rn(Oa[nt][0] * inv0, Oa[nt][1] * inv0);
        *reinterpret_cast<__half2*>(o1 + d) = __floats2half2_rn(Oa[nt][2] * inv1, Oa[nt][3] * inv1);
    }
}

// =============== mega-prep: detect+bias | LN1 rows | weight converts ============
__global__ void __launch_bounds__(256) prep_all(
    const int* __restrict__ adj,
    const float* __restrict__ bq, const float* __restrict__ bk,
    const float* __restrict__ bv, float* __restrict__ bqkv,
    const float* __restrict__ X, const float* __restrict__ g1,
    const float* __restrict__ be1, __half* __restrict__ Y,
    const float* __restrict__ Wq, const float* __restrict__ Wk,
    const float* __restrict__ Wv, const float* __restrict__ Wo,
    const float* __restrict__ W1, const float* __restrict__ W2,
    __half* __restrict__ dqkv, __half* __restrict__ dwo,
    __half* __restrict__ dw1, __half* __restrict__ dw2)
{
    const int bx = blockIdx.x, tid = threadIdx.x;
    if (bx == 0) {
        __shared__ int flag;
        if (tid == 0) flag = 0;
        __syncthreads();
        for (int i = tid; i < 8192; i += 256)
            if (adj[2*i + 1] != 0) flag = 1;
        __syncthreads();
        if (tid == 0) g_adj_is32 = flag;
        for (int i = tid; i < 1536; i += 256)
            bqkv[i] = (i < 512) ? bq[i] : (i < 1024 ? bk[i - 512] : bv[i - 1024]);
        return;
    }
    if (bx <= MR) {
        int row = bx - 1;
        const float* x = X + (size_t)row * Dd;
        float v0 = x[tid], v1 = x[tid + 256];
        __shared__ float red1[8], red2[8];
        float s = v0 + v1;
        #pragma unroll
        for (int o = 16; o; o >>= 1) s += __shfl_xor_sync(0xffffffffu, s, o);
        if ((tid & 31) == 0) red1[tid >> 5] = s;
        __syncthreads();
        float tot = red1[0]+red1[1]+red1[2]+red1[3]+red1[4]+red1[5]+red1[6]+red1[7];
        float mu = tot * (1.0f / 512.0f);
        float d0 = v0 - mu, d1 = v1 - mu;
        float s2 = d0*d0 + d1*d1;
        #pragma unroll
        for (int o = 16; o; o >>= 1) s2 += __shfl_xor_sync(0xffffffffu, s2, o);
        if ((tid & 31) == 0) red2[tid >> 5] = s2;
        __syncthreads();
        float tot2 = red2[0]+red2[1]+red2[2]+red2[3]+red2[4]+red2[5]+red2[6]+red2[7];
        float inv = rsqrtf(tot2 * (1.0f / 512.0f) + 1e-5f);
        Y[(size_t)row*Dd + tid      ] = __float2half_rn(d0 * inv * g1[tid      ] + be1[tid      ]);
        Y[(size_t)row*Dd + tid + 256] = __float2half_rn(d1 * inv * g1[tid + 256] + be1[tid + 256]);
        return;
    }
    int t = bx - MR - 1;   // 0..3071
    const float* in; __half* out; int K, N, bxt, byt;
    if (t < 1024) {
        int z = t >> 8, r = t & 255;
        const float* srcs[4] = {Wq, Wk, Wv, Wo};
        __half* dsts[4] = {dqkv, dqkv + (size_t)Dd*Dd, dqkv + (size_t)2*Dd*Dd, dwo};
        in = srcs[z]; out = dsts[z]; K = Dd; N = Dd;
        bxt = (r & 15) * 32; byt = (r >> 4) * 32;
    } else if (t < 2048) {
        int r = t - 1024;
        in = W1; out = dw1; K = Dd; N = DFF;
        bxt = (r & 63) * 32; byt = (r >> 6) * 32;
    } else {
        int r = t - 2048;
        in = W2; out = dw2; K = DFF; N = Dd;
        bxt = (r & 15) * 32; byt = (r >> 4) * 32;
    }
    __shared__ float tt[32][33];
    int tx = tid & 31, ty = tid >> 5;
    #pragma unroll
    for (int i = 0; i < 32; i += 8)
        tt[ty + i][tx] = in[(size_t)(byt + ty + i) * N + bxt + tx];
    __syncthreads();
    #pragma unroll
    for (int i = 0; i < 32; i += 8)
        out[(size_t)(bxt + ty + i) * K + byt + tx] = __float2half_rn(tt[tx][ty + i]);
}

// =============== pack+vtrans: adj pack | V fragment-order transpose ==============
__global__ void __launch_bounds__(256) pack_vt(
    const int* __restrict__ adj32, const float* __restrict__ mask,
    uint8_t* __restrict__ out, const __half* __restrict__ V, __half* __restrict__ VTf)
{
    const int bx = blockIdx.x, tid = threadIdx.x;
    if (bx < 2048) {
        const int is32 = g_adj_is32;
        int base = (bx * 256 + tid) * 8;
        int b = base >> 18;
        int rem = base & (Nn * Nn - 1);
        int q = rem >> 9;
        float mq = mask[b * Nn + q];
        const float* mkp = mask + b * Nn;
        int k0 = rem & 511;
        uchar4 o[2];
        #pragma unroll
        for (int e = 0; e < 8; e++) {
            int i = base + e;
            int tv = is32 ? adj32[i] : adj32[2 * i];
            float mk = mkp[k0 + e];
            uint8_t v = (mq * mk == 0.0f) ? (uint8_t)40 : (uint8_t)(tv << 3);
            ((uint8_t*)o)[e] = v;
        }
        *reinterpret_cast<uchar4*>(out + base)     = o[0];
        *reinterpret_cast<uchar4*>(out + base + 4) = o[1];
        return;
    }
    // V fragment-order transpose tile: (bh, ktile) -> 64 d-rows of 128B
    int t = bx - 2048;          // 0..1023
    int bh = t >> 3, ktile = t & 7, nb = ktile * 64;
    int tx = tid & 31, ty = tid >> 5;
    __shared__ __half tb[64][65];
    const __half2* src = reinterpret_cast<const __half2*>(V + ((size_t)bh*Nn + nb) * HDm);
    #pragma unroll
    for (int i = 0; i < 8; i++) {
        int n = ty + i * 8;
        __half2 v = src[n * 32 + tx];
        tb[n][2*tx] = __low2half(v); tb[n][2*tx+1] = __high2half(v);
    }
    __syncthreads();
    __half2* dst = reinterpret_cast<__half2*>(VTf);
    #pragma unroll
    for (int i = 0; i < 8; i++) {
        int d = ty + i * 8;
        __half2 o = __halves2half2(tb[2*tx][d], tb[2*tx+1][d]);
        int g = tx >> 2, lr2 = tx & 3;                 // k pair = 8g + 2*lr2
        int p = (lr2 * 8 + g) ^ ((d & 7) << 2);
        dst[(((size_t)bh * HDm + d) * 8 + ktile) * 32 + p] = o;
    }
}

// ---------------- LayerNorm (standalone, for LN2) ----------------
__global__ __launch_bounds__(256) void ln_kernel(
    const float* __restrict__ X, const float* __restrict__ g,
    const float* __restrict__ beta, __half* __restrict__ Y)
{
    int row = blockIdx.x;
    const float* x = X + (size_t)row * Dd;
    int tid = threadIdx.x;
    float v0 = x[tid], v1 = x[tid + 256];

    __shared__ float red1[8], red2[8];
    float s = v0 + v1;
    #pragma unroll
    for (int o = 16; o; o >>= 1) s += __shfl_xor_sync(0xffffffffu, s, o);
    if ((tid & 31) == 0) red1[tid >> 5] = s;
    __syncthreads();
    float tot = red1[0]+red1[1]+red1[2]+red1[3]+red1[4]+red1[5]+red1[6]+red1[7];
    float mu = tot * (1.0f / 512.0f);

    float d0 = v0 - mu, d1 = v1 - mu;
    float s2 = d0*d0 + d1*d1;
    #pragma unroll
    for (int o = 16; o; o >>= 1) s2 += __shfl_xor_sync(0xffffffffu, s2, o);
    if ((tid & 31) == 0) red2[tid >> 5] = s2;
    __syncthreads();
    float tot2 = red2[0]+red2[1]+red2[2]+red2[3]+red2[4]+red2[5]+red2[6]+red2[7];
    float inv = rsqrtf(tot2 * (1.0f / 512.0f) + 1e-5f);

    Y[(size_t)row*Dd + tid      ] = __float2half_rn(d0 * inv * g[tid      ] + beta[tid      ]);
    Y[(size_t)row*Dd + tid + 256] = __float2half_rn(d1 * inv * g[tid + 256] + beta[tid + 256]);
}

// ---------------------------------- launch ----------------------------------
extern "C" void kernel_launch(void* const* d_in, const int* in_sizes, int n_in,
                              void* d_out, int out_size)
{
    const float* x    = (const float*)d_in[0];
    const int*   adj  = (const int*)  d_in[1];
    const float* mask = (const float*)d_in[2];
    const float* Wq   = (const float*)d_in[3];
    const float* bq   = (const float*)d_in[4];
    const float* Wk   = (const float*)d_in[5];
    const float* bk   = (const float*)d_in[6];
    const float* Wv   = (const float*)d_in[7];
    const float* bv   = (const float*)d_in[8];
    const float* Wo   = (const float*)d_in[9];
    const float* bo   = (const float*)d_in[10];
    const float* eb   = (const float*)d_in[11];
    const float* W1   = (const float*)d_in[12];
    const float* b1   = (const float*)d_in[13];
    const float* W2   = (const float*)d_in[14];
    const float* b2   = (const float*)d_in[15];
    const float* g1   = (const float*)d_in[16];
    const float* be1  = (const float*)d_in[17];
    const float* g2   = (const float*)d_in[18];
    const float* be2  = (const float*)d_in[19];
    float* out = (float*)d_out;

    __half *h1, *QKh, *Vh, *VTf, *O, *h2, *mid;
    __half *Wqkvh, *WoTh, *W1Th, *W2Th;
    float *x1, *bqkv;
    uint8_t* adjm;
    cudaGetSymbolAddress((void**)&h1,   g_h1);
    cudaGetSymbolAddress((void**)&QKh,  g_QKh);
    cudaGetSymbolAddress((void**)&Vh,   g_Vh);
    cudaGetSymbolAddress((void**)&VTf,  g_VTf);
    cudaGetSymbolAddress((void**)&O,    g_O);
    cudaGetSymbolAddress((void**)&x1,   g_x1);
    cudaGetSymbolAddress((void**)&h2,   g_h2);
    cudaGetSymbolAddress((void**)&mid,  g_mid);
    cudaGetSymbolAddress((void**)&Wqkvh,g_Wqkvh);
    cudaGetSymbolAddress((void**)&WoTh, g_WoTh);
    cudaGetSymbolAddress((void**)&W1Th, g_W1Th);
    cudaGetSymbolAddress((void**)&W2Th, g_W2Th);
    cudaGetSymbolAddress((void**)&bqkv, g_bqkv);
    cudaGetSymbolAddress((void**)&adjm, g_adjm);

    static int attr_set = 0;
    if (!attr_set) {
        cudaFuncSetAttribute(hgemm<0>, cudaFuncAttributeMaxDynamicSharedMemorySize, DENSE_SMEM);
        cudaFuncSetAttribute(hgemm<1>, cudaFuncAttributeMaxDynamicSharedMemorySize, DENSE_SMEM);
        cudaFuncSetAttribute(hgemm<2>, cudaFuncAttributeMaxDynamicSharedMemorySize, DENSE_SMEM);
        cudaFuncSetAttribute(hgemm<3>, cudaFuncAttributeMaxDynamicSharedMemorySize, DENSE_SMEM);
        cudaFuncSetAttribute(attn_fused, cudaFuncAttributeMaxDynamicSharedMemorySize, FA_SMEM);
        attr_set = 1;
    }

    // 0: mega-prep (detect + bias + LN1 + all weight converts)
    prep_all<<<1 + MR + 3072, 256>>>(adj, bq, bk, bv, bqkv,
                                     x, g1, be1, h1,
                                     Wq, Wk, Wv, Wo, W1, W2,
                                     Wqkvh, WoTh, W1Th, W2Th);
    // 1: fused QKV
    hgemm<0><<<dim3(12, 64), 256, DENSE_SMEM>>>(h1, Wqkvh, bqkv, nullptr, nullptr, QKh, Dd, 3*Dd);
    // 2: adj pack + V fragment-order transpose
    pack_vt<<<2048 + 1024, 256>>>(adj, mask, adjm, Vh, VTf);
    // 3: fused attention (profiled at capture index 3)
    const __half* Qp = QKh;
    const __half* Kp = QKh + (size_t)MR * Dd;
    attn_fused<<<dim3(4, Bb*Hh), 256, FA_SMEM>>>(Qp, Kp, VTf, eb, adjm, O);
    // 4: output projection + residual
    hgemm<1><<<dim3(4, 64), 256, DENSE_SMEM>>>(O, WoTh, bo, x, nullptr, x1, Dd, Dd);
    // 5: LN2
    ln_kernel<<<MR, 256>>>(x1, g2, be2, h2);
    // 6: FFN1 + gelu
    hgemm<2><<<dim3(16, 64), 256, DENSE_SMEM>>>(h2, W1Th, b1, nullptr, nullptr, mid, Dd, DFF);
    // 7: FFN2 + residual + mask
    hgemm<3><<<dim3(4, 64), 256, DENSE_SMEM>>>(mid, W2Th, b2, x1, mask, out, DFF, Dd);
}

// round 12
// speedup vs baseline: 1.1425x; 1.0503x over previous
#include <cuda_runtime.h>
#include <cuda_fp16.h>
#include <math.h>
#include <stdint.h>

#define Bb   16
#define Nn   512
#define Dd   512
#define Hh   8
#define HDm  64
#define MR   (Bb*Nn)
#define DFF  2048

// ---------------- scratch (static device globals) ----------------
__device__ __half g_h1 [MR*Dd];
__device__ __half g_QKh[2*MR*Dd];     // [2][B][H][N][HD]
__device__ __half g_Vh [MR*Dd];       // [B][H][N][HD]
__device__ __half g_VTf[MR*Dd];       // fragment-ordered V^T
__device__ __half g_O  [MR*Dd];       // (B,N,D) half
__device__ float  g_x1 [MR*Dd];
__device__ __half g_h2 [MR*Dd];
__device__ __half g_mid[MR*DFF];
__device__ __half g_Wqkvh[3*Dd*Dd];   // [1536][512] K-major
__device__ __half g_WoTh [Dd*Dd];
__device__ __half g_W1Th [DFF*Dd];
__device__ __half g_W2Th [Dd*DFF];
__device__ float  g_bqkv[3*Dd];
__device__ uint8_t g_adjm[(size_t)Bb*Nn*Nn];  // fragment-permuted adj/mask table
__device__ int    g_adj_is32;

#define LOG2E 1.44269504088896340736f

// ======================= helpers =======================
__device__ __forceinline__ uint32_t smem_u32(const void* p) {
    uint32_t a;
    asm("{ .reg .u64 t; cvta.to.shared.u64 t, %1; cvt.u32.u64 %0, t; }" : "=r"(a) : "l"(p));
    return a;
}
__device__ __forceinline__ void cp16h(void* s, const __half* g) {
    uint32_t sa = smem_u32(s);
    asm volatile("cp.async.cg.shared.global [%0], [%1], 16;" :: "r"(sa), "l"(g) : "memory");
}
#define CP_COMMIT() asm volatile("cp.async.commit_group;" ::: "memory")
#define CP_WAIT(n)  asm volatile("cp.async.wait_group %0;" :: "n"(n) : "memory")

__device__ __forceinline__ int swz3(int r) {          // bit-reverse of r&7
    return ((r & 1) << 2) | (r & 2) | ((r & 4) >> 2);
}
__device__ __forceinline__ uint32_t ex2h2(float a, float b) {
    __half2 h = __floats2half2_rn(a, b);
    uint32_t u = *reinterpret_cast<uint32_t*>(&h);
    uint32_t r;
    asm("ex2.approx.f16x2 %0, %1;" : "=r"(r) : "r"(u));
    return r;
}

// m16n8k16 fp16 mma, f32 accum, row.col
__device__ __forceinline__ void mma16(float* c, uint32_t a0, uint32_t a1, uint32_t a2,
                                      uint32_t a3, uint32_t b0, uint32_t b1) {
    asm volatile("mma.sync.aligned.m16n8k16.row.col.f32.f16.f16.f32 "
        "{%0,%1,%2,%3},{%4,%5,%6,%7},{%8,%9},{%0,%1,%2,%3};"
        : "+f"(c[0]), "+f"(c[1]), "+f"(c[2]), "+f"(c[3])
        : "r"(a0), "r"(a1), "r"(a2), "r"(a3), "r"(b0), "r"(b1));
}

// warp 32x64 tile compute over one 64-k plane pair (A rows at pa, B rows at pb)
__device__ __forceinline__ void plane_mma(const char* pa, const char* pb,
                                          float acc[2][8][4], int lq, int lr, int sl)
{
    #pragma unroll
    for (int sc = 0; sc < 2; sc++) {
        int go = ((sc * 4 + lr) ^ sl) << 4;
        uint4 Ar[2][2];
        #pragma unroll
        for (int mt = 0; mt < 2; mt++) {
            Ar[mt][0] = *reinterpret_cast<const uint4*>(pa + (mt*16 + lq    ) * 128 + go);
            Ar[mt][1] = *reinterpret_cast<const uint4*>(pa + (mt*16 + lq + 8) * 128 + go);
        }
        #pragma unroll
        for (int nt = 0; nt < 8; nt++) {
            uint4 Bv = *reinterpret_cast<const uint4*>(pb + (nt*8 + lq) * 128 + go);
            mma16(acc[0][nt], Ar[0][0].x, Ar[0][1].x, Ar[0][0].y, Ar[0][1].y, Bv.x, Bv.y);
            mma16(acc[1][nt], Ar[1][0].x, Ar[1][1].x, Ar[1][0].y, Ar[1][1].y, Bv.x, Bv.y);
            mma16(acc[0][nt], Ar[0][0].z, Ar[0][1].z, Ar[0][0].w, Ar[0][1].w, Bv.z, Bv.w);
            mma16(acc[1][nt], Ar[1][0].z, Ar[1][1].z, Ar[1][0].w, Ar[1][1].w, Bv.z, Bv.w);
        }
    }
}

// ======================= dense GEMM: R7-proven 2-stage, 2-sync ==================
#define DENSE_SMEM 65536

template<int MODE>
__global__ void __launch_bounds__(256, 2) hgemm(
    const __half* __restrict__ A, const __half* __restrict__ Wt,
    const float* __restrict__ bias, const float* __restrict__ res,
    const float* __restrict__ mask, void* Cv, int K, int ncols)
{
    extern __shared__ char sm[];
    const int tid = threadIdx.x, lane = tid & 31, warp = tid >> 5;
    const int wm = warp >> 1, wn = warp & 1, lq = lane >> 2, lr = lane & 3;
    const int bm = blockIdx.y * 128, bn = blockIdx.x * 128;
    const int sl = swz3(lq);

    float acc[2][8][4];
    #pragma unroll
    for (int i = 0; i < 2; i++)
        #pragma unroll
        for (int j = 0; j < 8; j++)
            #pragma unroll
            for (int l = 0; l < 4; l++) acc[i][j][l] = 0.0f;

    const int NC = K >> 6;

    auto loadc = [&](int c, int buf) {
        char* dA = sm + buf * 32768;
        char* dB = dA + 16384;
        int k0 = c << 6;
        #pragma unroll
        for (int i = 0; i < 4; i++) {
            int idx = tid + i * 256, row = idx >> 3, g = idx & 7;
            int gp = ((g ^ swz3(row & 7)) << 4);
            cp16h(dA + row * 128 + gp, A  + (size_t)(bm + row) * K + k0 + g * 8);
            cp16h(dB + row * 128 + gp, Wt + (size_t)(bn + row) * K + k0 + g * 8);
        }
    };
    loadc(0, 0); CP_COMMIT();
    loadc(1, 1); CP_COMMIT();

    for (int c = 0; c < NC; c++) {
        CP_WAIT(1);
        __syncthreads();
        const char* pa = sm + (c & 1) * 32768 + (wm * 32) * 128;
        const char* pb = sm + (c & 1) * 32768 + 16384 + (wn * 64) * 128;
        plane_mma(pa, pb, acc, lq, lr, sl);
        __syncthreads();
        if (c + 2 < NC) loadc(c + 2, c & 1);
        CP_COMMIT();
    }

    #pragma unroll
    for (int mt = 0; mt < 2; mt++) {
        #pragma unroll
        for (int hf = 0; hf < 2; hf++) {
            int r = bm + wm*32 + mt*16 + lq + hf*8;
            float mr = (MODE == 3) ? mask[r] : 0.0f;
            #pragma unroll
            for (int nt = 0; nt < 8; nt++) {
                int cg = bn + wn*64 + nt*8 + 2*lr;
                float v0 = acc[mt][nt][hf*2 + 0] + bias[cg];
                float v1 = acc[mt][nt][hf*2 + 1] + bias[cg + 1];
                if (MODE == 0) {
                    int mat = cg >> 9, cc = cg & 511, hh = cc >> 6, d0 = cc & 63;
                    int b = r >> 9, n = r & 511;
                    if (mat == 0) { v0 *= 0.125f*LOG2E; v1 *= 0.125f*LOG2E; }
                    __half2 hv = __floats2half2_rn(v0, v1);
                    if (mat < 2) {
                        __half* op = (__half*)Cv + ((((size_t)mat*Bb + b)*Hh + hh)*Nn + n)*HDm + d0;
                        *reinterpret_cast<__half2*>(op) = hv;
                    } else {
                        __half* vp = g_Vh + (((size_t)b*Hh + hh)*Nn + n)*HDm + d0;
                        *reinterpret_cast<__half2*>(vp) = hv;
                    }
                } else if (MODE == 1) {
                    float* C = (float*)Cv;
                    const float* rp = res + (size_t)r * ncols + cg;
                    float2 r2 = *reinterpret_cast<const float2*>(rp);
                    float2 o; o.x = v0 + r2.x; o.y = v1 + r2.y;
                    *reinterpret_cast<float2*>(C + (size_t)r * ncols + cg) = o;
                } else if (MODE == 2) {
                    __half* C = (__half*)Cv;
                    float o0 = 0.5f * v0 * (1.0f + erff(v0 * 0.70710678118654752f));
                    float o1 = 0.5f * v1 * (1.0f + erff(v1 * 0.70710678118654752f));
                    *reinterpret_cast<__half2*>(C + (size_t)r * ncols + cg) = __floats2half2_rn(o0, o1);
                } else {
                    float* C = (float*)Cv;
                    const float* rp = res + (size_t)r * ncols + cg;
                    float2 r2 = *reinterpret_cast<const float2*>(rp);
                    float2 o; o.x = (v0 + r2.x) * mr; o.y = (v1 + r2.y) * mr;
                    *reinterpret_cast<float2*>(C + (size_t)r * ncols + cg) = o;
                }
            }
        }
    }
}

// ======================= fused attention, base-2 softmax ========================
// adjm fragment-permuted: byte for (kt,nt,lr,j) at row offset kt*64 + lr*16 + nt*2 + j.
// Per warp per tile: 2x LDG.128 instead of 16x LDG.16.
#define FA_SMEM 49408

__global__ void __launch_bounds__(256, 2) attn_fused(
    const __half* __restrict__ Q, const __half* __restrict__ Kh,
    const __half* __restrict__ VTf, const float* __restrict__ ebias,
    const uint8_t* __restrict__ adjm, __half* __restrict__ O)
{
    extern __shared__ char sm[];
    char*  Qs  = sm;
    char*  Ks  = sm + 16384;
    char*  Vs  = sm + 32768;
    float* lut = (float*)(sm + 49152);

    const int tid = threadIdx.x, lane = tid & 31, w = tid >> 5;
    const int lq = lane >> 2, lr = lane & 3;
    const int bh = blockIdx.y, b = bh >> 3, h = bh & 7;
    const int qt = blockIdx.x * 128;
    const int sl = swz3(lq);

    #pragma unroll
    for (int i = 0; i < 4; i++) {
        int idx = tid + i * 256, row = idx >> 3, g = idx & 7;
        cp16h(Qs + row * 128 + ((g ^ swz3(row & 7)) << 4),
              Q + ((size_t)bh * Nn + qt + row) * HDm + g * 8);
    }
    #pragma unroll
    for (int i = 0; i < 2; i++) {
        int idx = tid + i * 256, row = idx >> 3, g = idx & 7;
        int gp = ((g ^ swz3(row & 7)) << 4);
        cp16h(Ks + row * 128 + gp, Kh + ((size_t)bh * Nn + row) * HDm + g * 8);
        cp16h(Vs + row * 128 + g * 16,
              VTf + (((size_t)bh * HDm + row) * 8 + 0) * 64 + g * 8);
    }
    if (tid < 48) lut[tid] = (tid < 40) ? (ebias[tid] * LOG2E) : -86561.7f;
    CP_COMMIT();
    #pragma unroll
    for (int i = 0; i < 2; i++) {
        int idx = tid + i * 256, row = idx >> 3, g = idx & 7;
        int gp = ((g ^ swz3(row & 7)) << 4);
        cp16h(Ks + 8192 + row * 128 + gp, Kh + ((size_t)bh * Nn + 64 + row) * HDm + g * 8);
        cp16h(Vs + 8192 + row * 128 + g * 16,
              VTf + (((size_t)bh * HDm + row) * 8 + 1) * 64 + g * 8);
    }
    CP_COMMIT();

    float Oa[8][4];
    #pragma unroll
    for (int i = 0; i < 8; i++)
        #pragma unroll
        for (int j = 0; j < 4; j++) Oa[i][j] = 0.0f;
    float m0 = -1e30f, m1 = -1e30f, l0 = 0.0f, l1 = 0.0f;

    const int q0 = qt + w * 16 + lq;
    const uint8_t* am0 = adjm + ((size_t)b * Nn + q0) * Nn + lr * 16;
    const uint8_t* am1 = am0 + (size_t)8 * Nn;
    const int xr = lq << 2;

    for (int t = 0; t < 8; t++) {
        CP_WAIT(1);
        __syncthreads();
        const char* Kb = Ks + (t & 1) * 8192;
        const char* Vb = Vs + (t & 1) * 8192;

        float Sa[8][4];
        #pragma unroll
        for (int i = 0; i < 8; i++)
            #pragma unroll
            for (int j = 0; j < 4; j++) Sa[i][j] = 0.0f;
        #pragma unroll
        for (int sc = 0; sc < 2; sc++) {
            int go = ((sc * 4 + lr) ^ sl) << 4;
            uint4 A0 = *reinterpret_cast<const uint4*>(Qs + (w*16 + lq    ) * 128 + go);
            uint4 A1 = *reinterpret_cast<const uint4*>(Qs + (w*16 + lq + 8) * 128 + go);
            #pragma unroll
            for (int nt = 0; nt < 8; nt++) {
                uint4 Bv = *reinterpret_cast<const uint4*>(Kb + (nt*8 + lq) * 128 + go);
                mma16(Sa[nt], A0.x, A1.x, A0.y, A1.y, Bv.x, Bv.y);
                mma16(Sa[nt], A0.z, A1.z, A0.w, A1.w, Bv.z, Bv.w);
            }
        }

        // ---- edge bias + mask: 2x LDG.128 of fragment-permuted table ----
        {
            uint4 E0 = *reinterpret_cast<const uint4*>(am0 + t * 64);
            uint4 E1 = *reinterpret_cast<const uint4*>(am1 + t * 64);
            const uint32_t* w0 = reinterpret_cast<const uint32_t*>(&E0);
            const uint32_t* w1 = reinterpret_cast<const uint32_t*>(&E1);
            #pragma unroll
            for (int nt = 0; nt < 8; nt++) {
                uint32_t v0 = w0[nt >> 1] >> ((nt & 1) * 16);
                uint32_t v1 = w1[nt >> 1] >> ((nt & 1) * 16);
                Sa[nt][0] += lut[(v0 & 0xFF) + h];
                Sa[nt][1] += lut[((v0 >> 8) & 0xFF) + h];
                Sa[nt][2] += lut[(v1 & 0xFF) + h];
                Sa[nt][3] += lut[((v1 >> 8) & 0xFF) + h];
            }
        }

        float tm0 = -1e30f, tm1 = -1e30f;
        #pragma unroll
        for (int nt = 0; nt < 8; nt++) {
            tm0 = fmaxf(tm0, fmaxf(Sa[nt][0], Sa[nt][1]));
            tm1 = fmaxf(tm1, fmaxf(Sa[nt][2], Sa[nt][3]));
        }
        tm0 = fmaxf(tm0, __shfl_xor_sync(0xffffffffu, tm0, 1));
        tm0 = fmaxf(tm0, __shfl_xor_sync(0xffffffffu, tm0, 2));
        tm1 = fmaxf(tm1, __shfl_xor_sync(0xffffffffu, tm1, 1));
        tm1 = fmaxf(tm1, __shfl_xor_sync(0xffffffffu, tm1, 2));
        float nm0 = fmaxf(m0, tm0), nm1 = fmaxf(m1, tm1);
        float c0 = exp2f(m0 - nm0), c1 = exp2f(m1 - nm1);

        uint32_t ph[8][2];
        float rs0 = 0.0f, rs1 = 0.0f;
        #pragma unroll
        for (int nt = 0; nt < 8; nt++) {
            ph[nt][0] = ex2h2(Sa[nt][0] - nm0, Sa[nt][1] - nm0);
            ph[nt][1] = ex2h2(Sa[nt][2] - nm1, Sa[nt][3] - nm1);
            float2 f0 = __half22float2(*reinterpret_cast<__half2*>(&ph[nt][0]));
            float2 f1 = __half22float2(*reinterpret_cast<__half2*>(&ph[nt][1]));
            rs0 += f0.x + f0.y;
            rs1 += f1.x + f1.y;
        }
        rs0 += __shfl_xor_sync(0xffffffffu, rs0, 1);
        rs0 += __shfl_xor_sync(0xffffffffu, rs0, 2);
        rs1 += __shfl_xor_sync(0xffffffffu, rs1, 1);
        rs1 += __shfl_xor_sync(0xffffffffu, rs1, 2);
        l0 = l0 * c0 + rs0; l1 = l1 * c1 + rs1;
        m0 = nm0; m1 = nm1;
        #pragma unroll
        for (int nt = 0; nt < 8; nt++) {
            Oa[nt][0] *= c0; Oa[nt][1] *= c0;
            Oa[nt][2] *= c1; Oa[nt][3] *= c1;
        }

        #pragma unroll
        for (int nt = 0; nt < 8; nt++) {
            const char* vr = Vb + (nt*8 + lq) * 128;
            uint4 B0 = *reinterpret_cast<const uint4*>(vr + (((lr*8    ) ^ xr) << 2));
            uint4 B1 = *reinterpret_cast<const uint4*>(vr + (((lr*8 + 4) ^ xr) << 2));
            mma16(Oa[nt], ph[0][0], ph[0][1], ph[1][0], ph[1][1], B0.x, B0.y);
            mma16(Oa[nt], ph[2][0], ph[2][1], ph[3][0], ph[3][1], B0.z, B0.w);
            mma16(Oa[nt], ph[4][0], ph[4][1], ph[5][0], ph[5][1], B1.x, B1.y);
            mma16(Oa[nt], ph[6][0], ph[6][1], ph[7][0], ph[7][1], B1.z, B1.w);
        }

        __syncthreads();
        if (t + 2 < 8) {
            int kt2 = t + 2;
            char* dK = Ks + (t & 1) * 8192;
            char* dV = Vs + (t & 1) * 8192;
            #pragma unroll
            for (int i = 0; i < 2; i++) {
                int idx = tid + i * 256, row = idx >> 3, g = idx & 7;
                int gp = ((g ^ swz3(row & 7)) << 4);
                cp16h(dK + row * 128 + gp, Kh + ((size_t)bh * Nn + kt2*64 + row) * HDm + g * 8);
                cp16h(dV + row * 128 + g * 16,
                      VTf + (((size_t)bh * HDm + row) * 8 + kt2) * 64 + g * 8);
            }
        }
        CP_COMMIT();
    }

    float inv0 = (m0 > -7.0e4f) ? (1.0f / l0) : 0.0f;
    float inv1 = (m1 > -7.0e4f) ? (1.0f / l1) : 0.0f;
    __half* o0 = O + ((size_t)(b * Nn + q0)) * Dd + h * HDm;
    __half* o1 = o0 + (size_t)8 * Dd;
    #pragma unroll
    for (int nt = 0; nt < 8; nt++) {
        int d = nt * 8 + 2 * lr;
        *reinterpret_cast<__half2*>(o0 + d) = __floats2half2_rn(Oa[nt][0] * inv0, Oa[nt][1] * inv0);
        *reinterpret_cast<__half2*>(o1 + d) = __floats2half2_rn(Oa[nt][2] * inv1, Oa[nt][3] * inv1);
    }
}

// =============== mega-prep: detect+bias | LN1 rows | weight converts ============
__global__ void __launch_bounds__(256) prep_all(
    const int* __restrict__ adj,
    const float* __restrict__ bq, const float* __restrict__ bk,
    const float* __restrict__ bv, float* __restrict__ bqkv,
    const float* __restrict__ X, const float* __restrict__ g1,
    const float* __restrict__ be1, __half* __restrict__ Y,
    const float* __restrict__ Wq, const float* __restrict__ Wk,
    const float* __restrict__ Wv, const float* __restrict__ Wo,
    const float* __restrict__ W1, const float* __restrict__ W2,
    __half* __restrict__ dqkv, __half* __restrict__ dwo,
    __half* __restrict__ dw1, __half* __restrict__ dw2)
{
    const int bx = blockIdx.x, tid = threadIdx.x;
    if (bx == 0) {
        __shared__ int flag;
        if (tid == 0) flag = 0;
        __syncthreads();
        for (int i = tid; i < 8192; i += 256)
            if (adj[2*i + 1] != 0) flag = 1;
        __syncthreads();
        if (tid == 0) g_adj_is32 = flag;
        for (int i = tid; i < 1536; i += 256)
            bqkv[i] = (i < 512) ? bq[i] : (i < 1024 ? bk[i - 512] : bv[i - 1024]);
        return;
    }
    if (bx <= MR) {
        int row = bx - 1;
        const float* x = X + (size_t)row * Dd;
        float v0 = x[tid], v1 = x[tid + 256];
        __shared__ float red1[8], red2[8];
        float s = v0 + v1;
        #pragma unroll
        for (int o = 16; o; o >>= 1) s += __shfl_xor_sync(0xffffffffu, s, o);
        if ((tid & 31) == 0) red1[tid >> 5] = s;
        __syncthreads();
        float tot = red1[0]+red1[1]+red1[2]+red1[3]+red1[4]+red1[5]+red1[6]+red1[7];
        float mu = tot * (1.0f / 512.0f);
        float d0 = v0 - mu, d1 = v1 - mu;
        float s2 = d0*d0 + d1*d1;
        #pragma unroll
        for (int o = 16; o; o >>= 1) s2 += __shfl_xor_sync(0xffffffffu, s2, o);
        if ((tid & 31) == 0) red2[tid >> 5] = s2;
        __syncthreads();
        float tot2 = red2[0]+red2[1]+red2[2]+red2[3]+red2[4]+red2[5]+red2[6]+red2[7];
        float inv = rsqrtf(tot2 * (1.0f / 512.0f) + 1e-5f);
        Y[(size_t)row*Dd + tid      ] = __float2half_rn(d0 * inv * g1[tid      ] + be1[tid      ]);
        Y[(size_t)row*Dd + tid + 256] = __float2half_rn(d1 * inv * g1[tid + 256] + be1[tid + 256]);
        return;
    }
    int t = bx - MR - 1;   // 0..3071
    const float* in; __half* out; int K, N, bxt, byt;
    if (t < 1024) {
        int z = t >> 8, r = t & 255;
        const float* srcs[4] = {Wq, Wk, Wv, Wo};
        __half* dsts[4] = {dqkv, dqkv + (size_t)Dd*Dd, dqkv + (size_t)2*Dd*Dd, dwo};
        in = srcs[z]; out = dsts[z]; K = Dd; N = Dd;
        bxt = (r & 15) * 32; byt = (r >> 4) * 32;
    } else if (t < 2048) {
        int r = t - 1024;
        in = W1; out = dw1; K = Dd; N = DFF;
        bxt = (r & 63) * 32; byt = (r >> 6) * 32;
    } else {
        int r = t - 2048;
        in = W2; out = dw2; K = DFF; N = Dd;
        bxt = (r & 15) * 32; byt = (r >> 4) * 32;
    }
    __shared__ float tt[32][33];
    int tx = tid & 31, ty = tid >> 5;
    #pragma unroll
    for (int i = 0; i < 32; i += 8)
        tt[ty + i][tx] = in[(size_t)(byt + ty + i) * N + bxt + tx];
    __syncthreads();
    #pragma unroll
    for (int i = 0; i < 32; i += 8)
        out[(size_t)(bxt + ty + i) * K + byt + tx] = __float2half_rn(tt[tx][ty + i]);
}

// =============== pack+vtrans: fragment-permuted adj pack | V transpose ===========
__global__ void __launch_bounds__(256) pack_vt(
    const int* __restrict__ adj32, const float* __restrict__ mask,
    uint8_t* __restrict__ out, const __half* __restrict__ V, __half* __restrict__ VTf)
{
    const int bx = blockIdx.x, tid = threadIdx.x;
    if (bx < 2048) {
        // adj pack, output-contiguous in fragment-permuted layout:
        // within each row's 64B tile kt: pos = lr*16 + nt*2 + j holds k = kt*64+nt*8+2lr+j
        const int is32 = g_adj_is32;
        int base = (bx * 256 + tid) * 8;       // output byte index
        int b = base >> 18;
        int rem = base & (Nn * Nn - 1);
        int q = rem >> 9;
        int o = rem & 511;
        int kt = o >> 6, po = o & 63;
        int lr = po >> 4, sub = po & 15;       // sub in {0, 8}
        float mq = mask[b * Nn + q];
        const float* mkp = mask + b * Nn;
        size_t irow = ((size_t)b * Nn + q) * Nn;
        uchar4 ob[2];
        #pragma unroll
        for (int e = 0; e < 8; e++) {
            int pe = sub + e;
            int nt = pe >> 1, j = pe & 1;
            int k = kt * 64 + nt * 8 + 2 * lr + j;
            int tv = is32 ? adj32[irow + k] : adj32[2 * (irow + k)];
            float mk = mkp[k];
            ((uint8_t*)ob)[e] = (mq * mk == 0.0f) ? (uint8_t)40 : (uint8_t)(tv << 3);
        }
        *reinterpret_cast<uchar4*>(out + base)     = ob[0];
        *reinterpret_cast<uchar4*>(out + base + 4) = ob[1];
        return;
    }
    // V fragment-order transpose tile: (bh, ktile) -> 64 d-rows of 128B
    int t = bx - 2048;          // 0..1023
    int bh = t >> 3, ktile = t & 7, nb = ktile * 64;
    int tx = tid & 31, ty = tid >> 5;
    __shared__ __half tb[64][65];
    const __half2* src = reinterpret_cast<const __half2*>(V + ((size_t)bh*Nn + nb) * HDm);
    #pragma unroll
    for (int i = 0; i < 8; i++) {
        int n = ty + i * 8;
        __half2 v = src[n * 32 + tx];
        tb[n][2*tx] = __low2half(v); tb[n][2*tx+1] = __high2half(v);
    }
    __syncthreads();
    __half2* dst = reinterpret_cast<__half2*>(VTf);
    #pragma unroll
    for (int i = 0; i < 8; i++) {
        int d = ty + i * 8;
        __half2 o = __halves2half2(tb[2*tx][d], tb[2*tx+1][d]);
        int g = tx >> 2, lr2 = tx & 3;
        int p = (lr2 * 8 + g) ^ ((d & 7) << 2);
        dst[(((size_t)bh * HDm + d) * 8 + ktile) * 32 + p] = o;
    }
}

// ---------------- LayerNorm (standalone, for LN2) ----------------
__global__ __launch_bounds__(256) void ln_kernel(
    const float* __restrict__ X, const float* __restrict__ g,
    const float* __restrict__ beta, __half* __restrict__ Y)
{
    int row = blockIdx.x;
    const float* x = X + (size_t)row * Dd;
    int tid = threadIdx.x;
    float v0 = x[tid], v1 = x[tid + 256];

    __shared__ float red1[8], red2[8];
    float s = v0 + v1;
    #pragma unroll
    for (int o = 16; o; o >>= 1) s += __shfl_xor_sync(0xffffffffu, s, o);
    if ((tid & 31) == 0) red1[tid >> 5] = s;
    __syncthreads();
    float tot = red1[0]+red1[1]+red1[2]+red1[3]+red1[4]+red1[5]+red1[6]+red1[7];
    float mu = tot * (1.0f / 512.0f);

    float d0 = v0 - mu, d1 = v1 - mu;
    float s2 = d0*d0 + d1*d1;
    #pragma unroll
    for (int o = 16; o; o >>= 1) s2 += __shfl_xor_sync(0xffffffffu, s2, o);
    if ((tid & 31) == 0) red2[tid >> 5] = s2;
    __syncthreads();
    float tot2 = red2[0]+red2[1]+red2[2]+red2[3]+red2[4]+red2[5]+red2[6]+red2[7];
    float inv = rsqrtf(tot2 * (1.0f / 512.0f) + 1e-5f);

    Y[(size_t)row*Dd + tid      ] = __float2half_rn(d0 * inv * g[tid      ] + beta[tid      ]);
    Y[(size_t)row*Dd + tid + 256] = __float2half_rn(d1 * inv * g[tid + 256] + beta[tid + 256]);
}

// ---------------------------------- launch ----------------------------------
extern "C" void kernel_launch(void* const* d_in, const int* in_sizes, int n_in,
                              void* d_out, int out_size)
{
    const float* x    = (const float*)d_in[0];
    const int*   adj  = (const int*)  d_in[1];
    const float* mask = (const float*)d_in[2];
    const float* Wq   = (const float*)d_in[3];
    const float* bq   = (const float*)d_in[4];
    const float* Wk   = (const float*)d_in[5];
    const float* bk   = (const float*)d_in[6];
    const float* Wv   = (const float*)d_in[7];
    const float* bv   = (const float*)d_in[8];
    const float* Wo   = (const float*)d_in[9];
    const float* bo   = (const float*)d_in[10];
    const float* eb   = (const float*)d_in[11];
    const float* W1   = (const float*)d_in[12];
    const float* b1   = (const float*)d_in[13];
    const float* W2   = (const float*)d_in[14];
    const float* b2   = (const float*)d_in[15];
    const float* g1   = (const float*)d_in[16];
    const float* be1  = (const float*)d_in[17];
    const float* g2   = (const float*)d_in[18];
    const float* be2  = (const float*)d_in[19];
    float* out = (float*)d_out;

    __half *h1, *QKh, *Vh, *VTf, *O, *h2, *mid;
    __half *Wqkvh, *WoTh, *W1Th, *W2Th;
    float *x1, *bqkv;
    uint8_t* adjm;
    cudaGetSymbolAddress((void**)&h1,   g_h1);
    cudaGetSymbolAddress((void**)&QKh,  g_QKh);
    cudaGetSymbolAddress((void**)&Vh,   g_Vh);
    cudaGetSymbolAddress((void**)&VTf,  g_VTf);
    cudaGetSymbolAddress((void**)&O,    g_O);
    cudaGetSymbolAddress((void**)&x1,   g_x1);
    cudaGetSymbolAddress((void**)&h2,   g_h2);
    cudaGetSymbolAddress((void**)&mid,  g_mid);
    cudaGetSymbolAddress((void**)&Wqkvh,g_Wqkvh);
    cudaGetSymbolAddress((void**)&WoTh, g_WoTh);
    cudaGetSymbolAddress((void**)&W1Th, g_W1Th);
    cudaGetSymbolAddress((void**)&W2Th, g_W2Th);
    cudaGetSymbolAddress((void**)&bqkv, g_bqkv);
    cudaGetSymbolAddress((void**)&adjm, g_adjm);

    static int attr_set = 0;
    if (!attr_set) {
        cudaFuncSetAttribute(hgemm<0>, cudaFuncAttributeMaxDynamicSharedMemorySize, DENSE_SMEM);
        cudaFuncSetAttribute(hgemm<1>, cudaFuncAttributeMaxDynamicSharedMemorySize, DENSE_SMEM);
        cudaFuncSetAttribute(hgemm<2>, cudaFuncAttributeMaxDynamicSharedMemorySize, DENSE_SMEM);
        cudaFuncSetAttribute(hgemm<3>, cudaFuncAttributeMaxDynamicSharedMemorySize, DENSE_SMEM);
        cudaFuncSetAttribute(attn_fused, cudaFuncAttributeMaxDynamicSharedMemorySize, FA_SMEM);
        attr_set = 1;
    }

    // 0: mega-prep (detect + bias + LN1 + all weight converts)
    prep_all<<<1 + MR + 3072, 256>>>(adj, bq, bk, bv, bqkv,
                                     x, g1, be1, h1,
                                     Wq, Wk, Wv, Wo, W1, W2,
                                     Wqkvh, WoTh, W1Th, W2Th);
    // 1: fused QKV
    hgemm<0><<<dim3(12, 64), 256, DENSE_SMEM>>>(h1, Wqkvh, bqkv, nullptr, nullptr, QKh, Dd, 3*Dd);
    // 2: adj pack (fragment-permuted) + V fragment-order transpose
    pack_vt<<<2048 + 1024, 256>>>(adj, mask, adjm, Vh, VTf);
    // 3: fused attention (profiled at capture index 3)
    const __half* Qp = QKh;
    const __half* Kp = QKh + (size_t)MR * Dd;
    attn_fused<<<dim3(4, Bb*Hh), 256, FA_SMEM>>>(Qp, Kp, VTf, eb, adjm, O);
    // 4: output projection + residual
    hgemm<1><<<dim3(4, 64), 256, DENSE_SMEM>>>(O, WoTh, bo, x, nullptr, x1, Dd, Dd);
    // 5: LN2
    ln_kernel<<<MR, 256>>>(x1, g2, be2, h2);
    // 6: FFN1 + gelu
    hgemm<2><<<dim3(16, 64), 256, DENSE_SMEM>>>(h2, W1Th, b1, nullptr, nullptr, mid, Dd, DFF);
    // 7: FFN2 + residual + mask
    hgemm<3><<<dim3(4, 64), 256, DENSE_SMEM>>>(mid, W2Th, b2, x1, mask, out, DFF, Dd);
}